// round 12
// baseline (speedup 1.0000x reference)
#include <cuda_runtime.h>
#include <cuda_bf16.h>
#include <cuda_fp16.h>
#include <cstdint>
#include <cstddef>

// ---------------------------------------------------------------------------
// Problem constants
// ---------------------------------------------------------------------------
constexpr int BATCH = 4;
constexpr int TSEQ  = 8192;
constexpr int CDIM  = 2048;
constexpr int DHEAD = 128;
constexpr int NBLK  = 64;            // TSEQ / 128
constexpr int MROWS = BATCH * TSEQ;  // 32768
constexpr int N_QKV = 3 * CDIM;      // 6144
constexpr int NHEAD = 16;

// ---------------------------------------------------------------------------
// Static scratch (no allocations allowed)
// ---------------------------------------------------------------------------
__device__ __align__(256) __half g_X  [(size_t)MROWS * CDIM];
__device__ __align__(256) __half g_Wq [(size_t)CDIM * N_QKV];   // [K][N] native
__device__ __align__(256) __half g_Wp [(size_t)CDIM * CDIM];    // [K][N] native
__device__ __align__(256) __half g_QKV[(size_t)MROWS * N_QKV];  // fp16 intermediates
__device__ __align__(256) __half g_A  [(size_t)MROWS * CDIM];

// ---------------------------------------------------------------------------
// Helpers
// ---------------------------------------------------------------------------
__device__ __forceinline__ uint32_t smem_u32(const void* p) {
    return (uint32_t)__cvta_generic_to_shared(p);
}
__device__ __forceinline__ void cp16s(uint32_t s, const void* g) {
    asm volatile("cp.async.cg.shared.global [%0], [%1], 16;" :: "r"(s), "l"(g));
}
__device__ __forceinline__ void cp_commit() {
    asm volatile("cp.async.commit_group;");
}
template <int N>
__device__ __forceinline__ void cp_wait() {
    asm volatile("cp.async.wait_group %0;" :: "n"(N));
}

__device__ __forceinline__ uint32_t pkh2(__half a, __half b) {
    __half2 t; t.x = a; t.y = b;
    return *reinterpret_cast<uint32_t*>(&t);
}

__device__ __forceinline__ void ldsm4a(uint32_t* d, uint32_t a) {
    asm volatile("ldmatrix.sync.aligned.m8n8.x4.shared.b16 {%0,%1,%2,%3}, [%4];"
                 : "=r"(d[0]), "=r"(d[1]), "=r"(d[2]), "=r"(d[3]) : "r"(a));
}
__device__ __forceinline__ void ldsm4ta(uint32_t* d, uint32_t a) {
    asm volatile("ldmatrix.sync.aligned.m8n8.x4.trans.shared.b16 {%0,%1,%2,%3}, [%4];"
                 : "=r"(d[0]), "=r"(d[1]), "=r"(d[2]), "=r"(d[3]) : "r"(a));
}
__device__ __forceinline__ void ldsm2a(uint32_t* d, uint32_t a) {
    asm volatile("ldmatrix.sync.aligned.m8n8.x2.shared.b16 {%0,%1}, [%2];"
                 : "=r"(d[0]), "=r"(d[1]) : "r"(a));
}
__device__ __forceinline__ void ldsm2ta(uint32_t* d, uint32_t a) {
    asm volatile("ldmatrix.sync.aligned.m8n8.x2.trans.shared.b16 {%0,%1}, [%2];"
                 : "=r"(d[0]), "=r"(d[1]) : "r"(a));
}
// fp16 mma
__device__ __forceinline__ void mma_h(float* c, const uint32_t* a, const uint32_t* b) {
    asm volatile(
        "mma.sync.aligned.m16n8k16.row.col.f32.f16.f16.f32 "
        "{%0,%1,%2,%3}, {%4,%5,%6,%7}, {%8,%9}, {%0,%1,%2,%3};"
        : "+f"(c[0]), "+f"(c[1]), "+f"(c[2]), "+f"(c[3])
        : "r"(a[0]), "r"(a[1]), "r"(a[2]), "r"(a[3]), "r"(b[0]), "r"(b[1]));
}

// ---------------------------------------------------------------------------
// fp32 -> fp16 (single, RN)
// ---------------------------------------------------------------------------
__global__ void cvt_h_kernel(const float4* __restrict__ src,
                             uint32_t* __restrict__ dst, int n4) {
    int i = blockIdx.x * blockDim.x + threadIdx.x;
    if (i >= n4) return;
    float4 v = src[i];
    dst[2 * i]     = pkh2(__float2half_rn(v.x), __float2half_rn(v.y));
    dst[2 * i + 1] = pkh2(__float2half_rn(v.z), __float2half_rn(v.w));
}

// ---------------------------------------------------------------------------
// fp16 single-pass GEMM: C[M,N] = A[M,K] @ B[K,N]
// BM=128, BN=256, BK=64, 3-stage cp.async ring.
// 256 threads = 8 warps (2m x 4n), warp tile 64x64, 1 CTA/SM (RF-bound).
// Halves L2->SMEM bytes/MAC vs the 128x128 tile (L2 cap was the binder).
// Register-level pipeline: fragments for k16 step kk+1 loaded during step kk.
// Stage layout (49152 B): A @0 (16KB: 128 rows x 128B SW128),
//                         B @16384 (32KB: 64 krows x 512B).
// OUT_HALF: write fp16 pairs to Ch; else fp32 to Cf.
// ---------------------------------------------------------------------------
constexpr int G_STAGE = 49152;
constexpr int G_BOFF  = 16384;
constexpr int G_SMEM  = 3 * G_STAGE;  // 147456

template <bool OUT_HALF>
__global__ void __launch_bounds__(256, 1) gemm_fp16(
    const __half* __restrict__ A, const __half* __restrict__ B,
    float* __restrict__ Cf, __half* __restrict__ Ch, int Nn, int Kk)
{
    extern __shared__ char smem[];
    const uint32_t sbase = smem_u32(smem);
    const int tid  = threadIdx.x;
    const int lane = tid & 31;
    const int wid  = tid >> 5;
    const int m0   = blockIdx.y * 128;
    const int n0   = blockIdx.x * 256;
    const int wm   = (wid >> 2) * 64;
    const int wn   = (wid & 3) * 64;

    // --- load geometry (base + stride; swizzle bits invariant under row step) ---
    // A: 128 rows x 8 chunks(16B) = 1024 tasks, 4 per thread, row step 32
    const int ra = tid >> 3, ca = tid & 7;
    const char* gA0 = (const char*)(A + (size_t)(m0 + ra) * Kk + ca * 8);
    const uint32_t sA0 = sbase + ra * 128 + ((ca ^ (ra & 7)) * 16);
    const size_t rowA = (size_t)32 * Kk * 2;       // +32 rows
    // B: 64 krows x 32 chunks(16B) = 2048 tasks, 8 per thread, krow step 8
    const int rb = tid >> 5, cb = tid & 31;
    const char* gB0 = (const char*)(B + (size_t)rb * Nn + n0 + cb * 8);
    const uint32_t sB0 = sbase + G_BOFF + rb * 512 + ((cb ^ (rb & 7)) * 16);
    const size_t rowB = (size_t)8 * Nn * 2;        // +8 krows

    const size_t stepA = 128;                      // k-tile: 64 halfs
    const size_t stepB = (size_t)64 * Nn * 2;

    const int NK = Kk / 64;

    // prologue: stages 0..1
#pragma unroll
    for (int s = 0; s < 2; s++) {
        uint32_t so = (uint32_t)(s * G_STAGE);
        const char* ga = gA0 + (size_t)s * stepA;
        const char* gb = gB0 + (size_t)s * stepB;
#pragma unroll
        for (int i = 0; i < 4; i++)
            cp16s(sA0 + so + i * (32 * 128), ga + (size_t)i * rowA);
#pragma unroll
        for (int i = 0; i < 8; i++)
            cp16s(sB0 + so + i * (8 * 512), gb + (size_t)i * rowB);
        cp_commit();
    }

    float c[4][8][4];
#pragma unroll
    for (int mt = 0; mt < 4; mt++)
#pragma unroll
        for (int nt = 0; nt < 8; nt++)
#pragma unroll
            for (int e = 0; e < 4; e++) c[mt][nt][e] = 0.f;

    uint32_t aa[2][4][4], bb[2][4][4];

    // fragment loader for k16 step kk from stage buffer sbuf
    auto load_frags = [&](uint32_t sbuf, int kk, int buf) {
#pragma unroll
        for (int p = 0; p < 4; p++) {
            int krow = kk * 16 + (lane & 15);
            int ch   = (wn >> 3) + p * 2 + (lane >> 4);
            int sw   = ch ^ (krow & 7);
            ldsm4ta(bb[buf][p], sbuf + G_BOFF + krow * 512 + sw * 16);
        }
#pragma unroll
        for (int mt = 0; mt < 4; mt++) {
            int r  = wm + mt * 16 + (lane & 15);
            int ch = kk * 2 + (lane >> 4);
            int sw = ch ^ (r & 7);
            ldsm4a(aa[buf][mt], sbuf + r * 128 + sw * 16);
        }
    };

    int sidx = 0;                            // stage index of kt
    for (int kt = 0; kt < NK; kt++) {
        cp_wait<1>();
        __syncthreads();

        const uint32_t sbuf = sbase + sidx * G_STAGE;

        // start fragment loads for kk=0 immediately (fill LSU early)
        load_frags(sbuf, 0, 0);

        // issue stage kt+2 (buffer last consumed in iter kt-1; safe after barrier)
        {
            int kn = kt + 2;
            if (kn < NK) {
                int sn = sidx + 2; if (sn >= 3) sn -= 3;
                uint32_t so = (uint32_t)(sn * G_STAGE);
                const char* ga = gA0 + (size_t)kn * stepA;
                const char* gb = gB0 + (size_t)kn * stepB;
#pragma unroll
                for (int i = 0; i < 4; i++)
                    cp16s(sA0 + so + i * (32 * 128), ga + (size_t)i * rowA);
#pragma unroll
                for (int i = 0; i < 8; i++)
                    cp16s(sB0 + so + i * (8 * 512), gb + (size_t)i * rowB);
            }
            cp_commit();
        }

#pragma unroll
        for (int kk = 0; kk < 4; kk++) {
            const int buf = kk & 1;
            // prefetch next step's fragments before consuming current ones
            if (kk < 3) load_frags(sbuf, kk + 1, buf ^ 1);
#pragma unroll
            for (int mt = 0; mt < 4; mt++)
#pragma unroll
                for (int p = 0; p < 4; p++) {
                    mma_h(c[mt][2 * p],     aa[buf][mt], &bb[buf][p][0]);
                    mma_h(c[mt][2 * p + 1], aa[buf][mt], &bb[buf][p][2]);
                }
        }
        sidx++; if (sidx >= 3) sidx = 0;
    }

    // epilogue
#pragma unroll
    for (int mt = 0; mt < 4; mt++) {
#pragma unroll
        for (int nt = 0; nt < 8; nt++) {
            int row = m0 + wm + mt * 16 + (lane >> 2);
            int col = n0 + wn + nt * 8 + (lane & 3) * 2;
            if (OUT_HALF) {
                *reinterpret_cast<uint32_t*>(Ch + (size_t)row * Nn + col) =
                    pkh2(__float2half_rn(c[mt][nt][0]), __float2half_rn(c[mt][nt][1]));
                *reinterpret_cast<uint32_t*>(Ch + (size_t)(row + 8) * Nn + col) =
                    pkh2(__float2half_rn(c[mt][nt][2]), __float2half_rn(c[mt][nt][3]));
            } else {
                *reinterpret_cast<float2*>(Cf + (size_t)row * Nn + col) =
                    make_float2(c[mt][nt][0], c[mt][nt][1]);
                *reinterpret_cast<float2*>(Cf + (size_t)(row + 8) * Nn + col) =
                    make_float2(c[mt][nt][2], c[mt][nt][3]);
            }
        }
    }
}

// ---------------------------------------------------------------------------
// Attention: one CTA per (b, blk, h). fp16 QKV in, single-pass fp16 mma,
// causal triangular skipping. smem: sQ/sK/sV each [128][128] fp16 = 96KB.
// ---------------------------------------------------------------------------
__global__ void __launch_bounds__(256, 1) attn_kernel(
    const __half* __restrict__ qkv, __half* __restrict__ att)
{
    extern __shared__ char smem[];
    __half* sQ = reinterpret_cast<__half*>(smem);            // [128][128]
    __half* sK = reinterpret_cast<__half*>(smem) + 16384;
    __half* sV = reinterpret_cast<__half*>(smem) + 32768;

    const int tid  = threadIdx.x;
    const int lane = tid & 31;
    const int wid  = tid >> 5;

    const int cta = blockIdx.x;
    const int h   = cta & 15;
    const int blk = (cta >> 4) & 63;
    const int b   = cta >> 10;
    const size_t t0 = (size_t)b * TSEQ + (size_t)blk * 128;

    // load Q,K,V: 3 tensors x 128 rows x 16 chunks(16B) = 6144 tasks
#pragma unroll
    for (int t = 0; t < 24; t++) {
        int idx = tid + t * 256;
        int tensor = idx >> 11;          // 0..2
        int rem = idx & 2047;
        int r  = rem >> 4;
        int ch = rem & 15;
        const __half* g = qkv + (t0 + r) * (size_t)N_QKV
                        + tensor * CDIM + h * DHEAD + ch * 8;
        __half* dstb = (tensor == 0) ? sQ : (tensor == 1) ? sK : sV;
        cp16s(smem_u32(dstb + r * 128 + ((ch ^ (r & 7)) * 8)), g);
    }
    cp_commit();
    cp_wait<0>();
    __syncthreads();

    // ----- S = Q K^T (warp tile 16 x 128), causal-skipped -----
    const int rw0  = wid * 16;
    const int nmax = 2 * wid + 2;        // key tiles needed (n8 granularity)

    float s[16][4];
#pragma unroll
    for (int nt = 0; nt < 16; nt++)
#pragma unroll
        for (int e = 0; e < 4; e++) s[nt][e] = 0.f;

#pragma unroll
    for (int kk = 0; kk < 8; kk++) {
        uint32_t q[4];
        {
            int r  = rw0 + (lane & 15);
            int ch = kk * 2 + (lane >> 4);
            int sw = ch ^ (r & 7);
            ldsm4a(q, smem_u32(sQ + r * 128 + sw * 8));
        }
        for (int nt = 0; nt < nmax; nt++) {
            uint32_t k[2];
            int l16  = lane & 15;
            int nrow = nt * 8 + (l16 & 7);
            int ch   = kk * 2 + (l16 >> 3);
            int sw   = ch ^ (nrow & 7);
            ldsm2a(k, smem_u32(sK + nrow * 128 + sw * 8));
            mma_h(s[nt], q, k);
        }
    }

    // ----- causal softmax (over valid tiles only) -----
    const float scale = 0.08838834764831845f;  // 1/sqrt(128)
    const int g  = lane >> 2;
    const int tq = lane & 3;
    const int r0 = rw0 + g;
    const int r1 = r0 + 8;

    float mx0 = -1e30f, mx1 = -1e30f;
    for (int nt = 0; nt < nmax; nt++) {
        int j0 = nt * 8 + tq * 2;
        int j1 = j0 + 1;
        float v;
        v = s[nt][0] * scale; if (j0 > r0) v = -1e30f; s[nt][0] = v; mx0 = fmaxf(mx0, v);
        v = s[nt][1] * scale; if (j1 > r0) v = -1e30f; s[nt][1] = v; mx0 = fmaxf(mx0, v);
        v = s[nt][2] * scale; if (j0 > r1) v = -1e30f; s[nt][2] = v; mx1 = fmaxf(mx1, v);
        v = s[nt][3] * scale; if (j1 > r1) v = -1e30f; s[nt][3] = v; mx1 = fmaxf(mx1, v);
    }
    mx0 = fmaxf(mx0, __shfl_xor_sync(0xffffffffu, mx0, 1));
    mx0 = fmaxf(mx0, __shfl_xor_sync(0xffffffffu, mx0, 2));
    mx1 = fmaxf(mx1, __shfl_xor_sync(0xffffffffu, mx1, 1));
    mx1 = fmaxf(mx1, __shfl_xor_sync(0xffffffffu, mx1, 2));

    float sum0 = 0.f, sum1 = 0.f;
    for (int nt = 0; nt < nmax; nt++) {
        s[nt][0] = __expf(s[nt][0] - mx0); sum0 += s[nt][0];
        s[nt][1] = __expf(s[nt][1] - mx0); sum0 += s[nt][1];
        s[nt][2] = __expf(s[nt][2] - mx1); sum1 += s[nt][2];
        s[nt][3] = __expf(s[nt][3] - mx1); sum1 += s[nt][3];
    }
    sum0 += __shfl_xor_sync(0xffffffffu, sum0, 1);
    sum0 += __shfl_xor_sync(0xffffffffu, sum0, 2);
    sum1 += __shfl_xor_sync(0xffffffffu, sum1, 1);
    sum1 += __shfl_xor_sync(0xffffffffu, sum1, 2);
    const float inv0 = 1.f / sum0;
    const float inv1 = 1.f / sum1;

    // ----- O = P V (P -> fp16 frags), key blocks kk < wid+1 -----
    float o[16][4];
#pragma unroll
    for (int nt = 0; nt < 16; nt++)
#pragma unroll
        for (int e = 0; e < 4; e++) o[nt][e] = 0.f;

    const int kmax = wid + 1;
    for (int kk = 0; kk < kmax; kk++) {
        uint32_t aP[4];
        aP[0] = pkh2(__float2half_rn(s[2 * kk][0]),     __float2half_rn(s[2 * kk][1]));
        aP[1] = pkh2(__float2half_rn(s[2 * kk][2]),     __float2half_rn(s[2 * kk][3]));
        aP[2] = pkh2(__float2half_rn(s[2 * kk + 1][0]), __float2half_rn(s[2 * kk + 1][1]));
        aP[3] = pkh2(__float2half_rn(s[2 * kk + 1][2]), __float2half_rn(s[2 * kk + 1][3]));
#pragma unroll
        for (int nt = 0; nt < 16; nt++) {
            uint32_t v[2];
            int l16  = lane & 15;
            int krow = kk * 16 + l16;
            int sw   = nt ^ (krow & 7);
            ldsm2ta(v, smem_u32(sV + krow * 128 + sw * 8));
            mma_h(o[nt], aP, v);
        }
    }

    // ----- epilogue: fp16 (input to proj GEMM) -----
    const size_t tok0 = t0 + r0;
    const size_t tok1 = t0 + r1;
#pragma unroll
    for (int nt = 0; nt < 16; nt++) {
        int col = h * DHEAD + nt * 8 + tq * 2;
        *reinterpret_cast<uint32_t*>(att + tok0 * CDIM + col) =
            pkh2(__float2half_rn(o[nt][0] * inv0), __float2half_rn(o[nt][1] * inv0));
        *reinterpret_cast<uint32_t*>(att + tok1 * CDIM + col) =
            pkh2(__float2half_rn(o[nt][2] * inv1), __float2half_rn(o[nt][3] * inv1));
    }
}

// ---------------------------------------------------------------------------
// Host launcher
// ---------------------------------------------------------------------------
extern "C" void kernel_launch(void* const* d_in, const int* in_sizes, int n_in,
                              void* d_out, int out_size) {
    const float* x  = (const float*)d_in[0];
    const float* wq = (const float*)d_in[1];
    const float* wp = (const float*)d_in[2];
    float* out = (float*)d_out;

    void *pX, *pWq, *pWp, *pQKV, *pA;
    cudaGetSymbolAddress(&pX,   g_X);
    cudaGetSymbolAddress(&pWq,  g_Wq);
    cudaGetSymbolAddress(&pWp,  g_Wp);
    cudaGetSymbolAddress(&pQKV, g_QKV);
    cudaGetSymbolAddress(&pA,   g_A);

    cudaFuncSetAttribute((const void*)gemm_fp16<true>,
                         cudaFuncAttributeMaxDynamicSharedMemorySize, G_SMEM);
    cudaFuncSetAttribute((const void*)gemm_fp16<false>,
                         cudaFuncAttributeMaxDynamicSharedMemorySize, G_SMEM);
    cudaFuncSetAttribute((const void*)attn_kernel,
                         cudaFuncAttributeMaxDynamicSharedMemorySize, 98304);

    // 1) X, Wq, Wp -> fp16
    {
        int n4 = (MROWS * CDIM) / 4;
        cvt_h_kernel<<<n4 / 256, 256>>>((const float4*)x, (uint32_t*)pX, n4);
    }
    {
        int n4 = (CDIM * N_QKV) / 4;
        cvt_h_kernel<<<n4 / 256, 256>>>((const float4*)wq, (uint32_t*)pWq, n4);
    }
    {
        int n4 = (CDIM * CDIM) / 4;
        cvt_h_kernel<<<n4 / 256, 256>>>((const float4*)wp, (uint32_t*)pWp, n4);
    }

    // 2) QKV = X @ Wq -> fp16
    {
        dim3 grid(N_QKV / 256, MROWS / 128);  // (24, 256)
        gemm_fp16<true><<<grid, 256, G_SMEM>>>(
            (const __half*)pX, (const __half*)pWq, nullptr, (__half*)pQKV,
            N_QKV, CDIM);
    }

    // 3) blocked causal attention -> fp16
    attn_kernel<<<BATCH * NBLK * NHEAD, 256, 98304>>>(
        (const __half*)pQKV, (__half*)pA);

    // 4) Y = A @ Wp -> fp32 final output
    {
        dim3 grid(CDIM / 256, MROWS / 128);   // (8, 256)
        gemm_fp16<false><<<grid, 256, G_SMEM>>>(
            (const __half*)pA, (const __half*)pWp, out, nullptr, CDIM, CDIM);
    }
}

// round 13
// speedup vs baseline: 1.1567x; 1.1567x over previous
#include <cuda_runtime.h>
#include <cuda_bf16.h>
#include <cuda_fp16.h>
#include <cstdint>
#include <cstddef>

// ---------------------------------------------------------------------------
// Problem constants
// ---------------------------------------------------------------------------
constexpr int BATCH = 4;
constexpr int TSEQ  = 8192;
constexpr int CDIM  = 2048;
constexpr int DHEAD = 128;
constexpr int NBLK  = 64;            // TSEQ / 128
constexpr int MROWS = BATCH * TSEQ;  // 32768
constexpr int N_QKV = 3 * CDIM;      // 6144
constexpr int NHEAD = 16;

// ---------------------------------------------------------------------------
// Static scratch (no allocations allowed)
// ---------------------------------------------------------------------------
__device__ __align__(256) __half g_X  [(size_t)MROWS * CDIM];
__device__ __align__(256) __half g_Wq [(size_t)CDIM * N_QKV];   // [K][N] native
__device__ __align__(256) __half g_Wp [(size_t)CDIM * CDIM];    // [K][N] native
__device__ __align__(256) __half g_QKV[(size_t)MROWS * N_QKV];  // fp16 intermediates
__device__ __align__(256) __half g_A  [(size_t)MROWS * CDIM];

// ---------------------------------------------------------------------------
// Helpers
// ---------------------------------------------------------------------------
__device__ __forceinline__ uint32_t smem_u32(const void* p) {
    return (uint32_t)__cvta_generic_to_shared(p);
}
__device__ __forceinline__ void cp16s(uint32_t s, const void* g) {
    asm volatile("cp.async.cg.shared.global [%0], [%1], 16;" :: "r"(s), "l"(g));
}
__device__ __forceinline__ void cp_commit() {
    asm volatile("cp.async.commit_group;");
}
template <int N>
__device__ __forceinline__ void cp_wait() {
    asm volatile("cp.async.wait_group %0;" :: "n"(N));
}

__device__ __forceinline__ uint32_t pkh2(__half a, __half b) {
    __half2 t; t.x = a; t.y = b;
    return *reinterpret_cast<uint32_t*>(&t);
}

__device__ __forceinline__ void ldsm4a(uint32_t* d, uint32_t a) {
    asm volatile("ldmatrix.sync.aligned.m8n8.x4.shared.b16 {%0,%1,%2,%3}, [%4];"
                 : "=r"(d[0]), "=r"(d[1]), "=r"(d[2]), "=r"(d[3]) : "r"(a));
}
__device__ __forceinline__ void ldsm4ta(uint32_t* d, uint32_t a) {
    asm volatile("ldmatrix.sync.aligned.m8n8.x4.trans.shared.b16 {%0,%1,%2,%3}, [%4];"
                 : "=r"(d[0]), "=r"(d[1]), "=r"(d[2]), "=r"(d[3]) : "r"(a));
}
__device__ __forceinline__ void ldsm2a(uint32_t* d, uint32_t a) {
    asm volatile("ldmatrix.sync.aligned.m8n8.x2.shared.b16 {%0,%1}, [%2];"
                 : "=r"(d[0]), "=r"(d[1]) : "r"(a));
}
__device__ __forceinline__ void ldsm2ta(uint32_t* d, uint32_t a) {
    asm volatile("ldmatrix.sync.aligned.m8n8.x2.trans.shared.b16 {%0,%1}, [%2];"
                 : "=r"(d[0]), "=r"(d[1]) : "r"(a));
}
// fp16 mma
__device__ __forceinline__ void mma_h(float* c, const uint32_t* a, const uint32_t* b) {
    asm volatile(
        "mma.sync.aligned.m16n8k16.row.col.f32.f16.f16.f32 "
        "{%0,%1,%2,%3}, {%4,%5,%6,%7}, {%8,%9}, {%0,%1,%2,%3};"
        : "+f"(c[0]), "+f"(c[1]), "+f"(c[2]), "+f"(c[3])
        : "r"(a[0]), "r"(a[1]), "r"(a[2]), "r"(a[3]), "r"(b[0]), "r"(b[1]));
}

// ---------------------------------------------------------------------------
// Fused fp32 -> fp16 (single, RN) for X, Wq, Wp in one launch
// ---------------------------------------------------------------------------
__global__ void cvt_all_kernel(const float4* __restrict__ sx, uint32_t* __restrict__ dx, int nx,
                               const float4* __restrict__ sq, uint32_t* __restrict__ dq, int nq,
                               const float4* __restrict__ sp, uint32_t* __restrict__ dp, int np) {
    int i = blockIdx.x * blockDim.x + threadIdx.x;
    const float4* src; uint32_t* dst; int j;
    if (i < nx)           { src = sx; dst = dx; j = i; }
    else if (i < nx + nq) { src = sq; dst = dq; j = i - nx; }
    else if (i < nx + nq + np) { src = sp; dst = dp; j = i - nx - nq; }
    else return;
    float4 v = src[j];
    dst[2 * j]     = pkh2(__float2half_rn(v.x), __float2half_rn(v.y));
    dst[2 * j + 1] = pkh2(__float2half_rn(v.z), __float2half_rn(v.w));
}

// ---------------------------------------------------------------------------
// fp16 single-pass GEMM: C[M,N] = A[M,K] @ B[K,N]
// BM=128, BN=128, BK=64, 3-stage cp.async ring.
// 128 threads = 4 warps (2m x 2n), warp tile 64x64, 2 CTAs/SM.
// Register pipeline (frags for kk+1 during kk) + cp.async issues spread
// across the four kk blocks (4 per block) to smooth LSU pressure.
// Stage layout (32768 B): A @0 (16KB: 128 rows x 128B SW128),
//                         B @16384 (16KB: 64 krows x 256B).
// OUT_HALF: write fp16 pairs to Ch; else fp32 to Cf.
// ---------------------------------------------------------------------------
constexpr int G_STAGE = 32768;
constexpr int G_BOFF  = 16384;
constexpr int G_SMEM  = 3 * G_STAGE;  // 98304

template <bool OUT_HALF>
__global__ void __launch_bounds__(128, 2) gemm_fp16(
    const __half* __restrict__ A, const __half* __restrict__ B,
    float* __restrict__ Cf, __half* __restrict__ Ch, int Nn, int Kk)
{
    extern __shared__ char smem[];
    const uint32_t sbase = smem_u32(smem);
    const int tid  = threadIdx.x;
    const int lane = tid & 31;
    const int wid  = tid >> 5;
    const int m0   = blockIdx.y * 128;
    const int n0   = blockIdx.x * 128;
    const int wm   = (wid >> 1) * 64;
    const int wn   = (wid & 1) * 64;

    // --- load geometry (base + stride; swizzle bits invariant under row step) ---
    const int ra = tid >> 3, ca = tid & 7;
    const char* gA0 = (const char*)(A + (size_t)(m0 + ra) * Kk + ca * 8);
    const uint32_t sA0 = sbase + ra * 128 + ((ca ^ (ra & 7)) * 16);
    const size_t rowA = (size_t)16 * Kk * 2;       // +16 rows
    const int rb = tid >> 4, cb = tid & 15;
    const char* gB0 = (const char*)(B + (size_t)rb * Nn + n0 + cb * 8);
    const uint32_t sB0 = sbase + G_BOFF + rb * 256 + ((cb ^ (rb & 7)) * 16);
    const size_t rowB = (size_t)8 * Nn * 2;        // +8 krows

    const size_t stepA = 128;                      // k-tile: 64 halfs
    const size_t stepB = (size_t)64 * Nn * 2;

    const int NK = Kk / 64;

    // prologue: stages 0..1
#pragma unroll
    for (int s = 0; s < 2; s++) {
        uint32_t so = (uint32_t)(s * G_STAGE);
        const char* ga = gA0 + (size_t)s * stepA;
        const char* gb = gB0 + (size_t)s * stepB;
#pragma unroll
        for (int i = 0; i < 8; i++)
            cp16s(sA0 + so + i * (16 * 128), ga + (size_t)i * rowA);
#pragma unroll
        for (int i = 0; i < 8; i++)
            cp16s(sB0 + so + i * (8 * 256), gb + (size_t)i * rowB);
        cp_commit();
    }

    float c[4][8][4];
#pragma unroll
    for (int mt = 0; mt < 4; mt++)
#pragma unroll
        for (int nt = 0; nt < 8; nt++)
#pragma unroll
            for (int e = 0; e < 4; e++) c[mt][nt][e] = 0.f;

    uint32_t aa[2][4][4], bb[2][4][4];

    // fragment loader for k16 step kk from stage buffer sbuf
    auto load_frags = [&](uint32_t sbuf, int kk, int buf) {
#pragma unroll
        for (int p = 0; p < 4; p++) {
            int krow = kk * 16 + (lane & 15);
            int ch   = (wn >> 3) + p * 2 + (lane >> 4);
            int sw   = ch ^ (krow & 7);
            ldsm4ta(bb[buf][p], sbuf + G_BOFF + krow * 256 + sw * 16);
        }
#pragma unroll
        for (int mt = 0; mt < 4; mt++) {
            int r  = wm + mt * 16 + (lane & 15);
            int ch = kk * 2 + (lane >> 4);
            int sw = ch ^ (r & 7);
            ldsm4a(aa[buf][mt], sbuf + r * 128 + sw * 16);
        }
    };

    int sidx = 0;                            // stage index of kt
    for (int kt = 0; kt < NK; kt++) {
        cp_wait<1>();
        __syncthreads();

        const uint32_t sbuf = sbase + sidx * G_STAGE;

        // start fragment loads for kk=0 immediately (fill LSU early)
        load_frags(sbuf, 0, 0);

        // next-stage pointers (issues spread across the kk blocks below)
        const int kn = kt + 2;
        const bool dold = (kn < NK);
        int sn = sidx + 2; if (sn >= 3) sn -= 3;
        const uint32_t so = (uint32_t)(sn * G_STAGE);
        const char* ga = gA0 + (size_t)kn * stepA;
        const char* gb = gB0 + (size_t)kn * stepB;

#pragma unroll
        for (int kk = 0; kk < 4; kk++) {
            const int buf = kk & 1;
            // prefetch next step's fragments before consuming current ones
            if (kk < 3) load_frags(sbuf, kk + 1, buf ^ 1);
            // 4 of the 16 next-stage cp.async issues per block
            if (dold) {
#pragma unroll
                for (int i = 2 * kk; i < 2 * kk + 2; i++) {
                    cp16s(sA0 + so + i * (16 * 128), ga + (size_t)i * rowA);
                    cp16s(sB0 + so + i * (8 * 256), gb + (size_t)i * rowB);
                }
            }
#pragma unroll
            for (int mt = 0; mt < 4; mt++)
#pragma unroll
                for (int p = 0; p < 4; p++) {
                    mma_h(c[mt][2 * p],     aa[buf][mt], &bb[buf][p][0]);
                    mma_h(c[mt][2 * p + 1], aa[buf][mt], &bb[buf][p][2]);
                }
        }
        cp_commit();
        sidx++; if (sidx >= 3) sidx = 0;
    }

    // epilogue
#pragma unroll
    for (int mt = 0; mt < 4; mt++) {
#pragma unroll
        for (int nt = 0; nt < 8; nt++) {
            int row = m0 + wm + mt * 16 + (lane >> 2);
            int col = n0 + wn + nt * 8 + (lane & 3) * 2;
            if (OUT_HALF) {
                *reinterpret_cast<uint32_t*>(Ch + (size_t)row * Nn + col) =
                    pkh2(__float2half_rn(c[mt][nt][0]), __float2half_rn(c[mt][nt][1]));
                *reinterpret_cast<uint32_t*>(Ch + (size_t)(row + 8) * Nn + col) =
                    pkh2(__float2half_rn(c[mt][nt][2]), __float2half_rn(c[mt][nt][3]));
            } else {
                *reinterpret_cast<float2*>(Cf + (size_t)row * Nn + col) =
                    make_float2(c[mt][nt][0], c[mt][nt][1]);
                *reinterpret_cast<float2*>(Cf + (size_t)(row + 8) * Nn + col) =
                    make_float2(c[mt][nt][2], c[mt][nt][3]);
            }
        }
    }
}

// ---------------------------------------------------------------------------
// Attention: one CTA per (b, blk, h). fp16 QKV in, single-pass fp16 mma,
// causal triangular skipping. smem: sQ/sK/sV each [128][128] fp16 = 96KB.
// ---------------------------------------------------------------------------
__global__ void __launch_bounds__(256, 1) attn_kernel(
    const __half* __restrict__ qkv, __half* __restrict__ att)
{
    extern __shared__ char smem[];
    __half* sQ = reinterpret_cast<__half*>(smem);            // [128][128]
    __half* sK = reinterpret_cast<__half*>(smem) + 16384;
    __half* sV = reinterpret_cast<__half*>(smem) + 32768;

    const int tid  = threadIdx.x;
    const int lane = tid & 31;
    const int wid  = tid >> 5;

    const int cta = blockIdx.x;
    const int h   = cta & 15;
    const int blk = (cta >> 4) & 63;
    const int b   = cta >> 10;
    const size_t t0 = (size_t)b * TSEQ + (size_t)blk * 128;

    // load Q,K,V: 3 tensors x 128 rows x 16 chunks(16B) = 6144 tasks
#pragma unroll
    for (int t = 0; t < 24; t++) {
        int idx = tid + t * 256;
        int tensor = idx >> 11;          // 0..2
        int rem = idx & 2047;
        int r  = rem >> 4;
        int ch = rem & 15;
        const __half* g = qkv + (t0 + r) * (size_t)N_QKV
                        + tensor * CDIM + h * DHEAD + ch * 8;
        __half* dstb = (tensor == 0) ? sQ : (tensor == 1) ? sK : sV;
        cp16s(smem_u32(dstb + r * 128 + ((ch ^ (r & 7)) * 8)), g);
    }
    cp_commit();
    cp_wait<0>();
    __syncthreads();

    // ----- S = Q K^T (warp tile 16 x 128), causal-skipped -----
    const int rw0  = wid * 16;
    const int nmax = 2 * wid + 2;        // key tiles needed (n8 granularity)

    float s[16][4];
#pragma unroll
    for (int nt = 0; nt < 16; nt++)
#pragma unroll
        for (int e = 0; e < 4; e++) s[nt][e] = 0.f;

#pragma unroll
    for (int kk = 0; kk < 8; kk++) {
        uint32_t q[4];
        {
            int r  = rw0 + (lane & 15);
            int ch = kk * 2 + (lane >> 4);
            int sw = ch ^ (r & 7);
            ldsm4a(q, smem_u32(sQ + r * 128 + sw * 8));
        }
        for (int nt = 0; nt < nmax; nt++) {
            uint32_t k[2];
            int l16  = lane & 15;
            int nrow = nt * 8 + (l16 & 7);
            int ch   = kk * 2 + (l16 >> 3);
            int sw   = ch ^ (nrow & 7);
            ldsm2a(k, smem_u32(sK + nrow * 128 + sw * 8));
            mma_h(s[nt], q, k);
        }
    }

    // ----- causal softmax (over valid tiles only) -----
    const float scale = 0.08838834764831845f;  // 1/sqrt(128)
    const int g  = lane >> 2;
    const int tq = lane & 3;
    const int r0 = rw0 + g;
    const int r1 = r0 + 8;

    float mx0 = -1e30f, mx1 = -1e30f;
    for (int nt = 0; nt < nmax; nt++) {
        int j0 = nt * 8 + tq * 2;
        int j1 = j0 + 1;
        float v;
        v = s[nt][0] * scale; if (j0 > r0) v = -1e30f; s[nt][0] = v; mx0 = fmaxf(mx0, v);
        v = s[nt][1] * scale; if (j1 > r0) v = -1e30f; s[nt][1] = v; mx0 = fmaxf(mx0, v);
        v = s[nt][2] * scale; if (j0 > r1) v = -1e30f; s[nt][2] = v; mx1 = fmaxf(mx1, v);
        v = s[nt][3] * scale; if (j1 > r1) v = -1e30f; s[nt][3] = v; mx1 = fmaxf(mx1, v);
    }
    mx0 = fmaxf(mx0, __shfl_xor_sync(0xffffffffu, mx0, 1));
    mx0 = fmaxf(mx0, __shfl_xor_sync(0xffffffffu, mx0, 2));
    mx1 = fmaxf(mx1, __shfl_xor_sync(0xffffffffu, mx1, 1));
    mx1 = fmaxf(mx1, __shfl_xor_sync(0xffffffffu, mx1, 2));

    float sum0 = 0.f, sum1 = 0.f;
    for (int nt = 0; nt < nmax; nt++) {
        s[nt][0] = __expf(s[nt][0] - mx0); sum0 += s[nt][0];
        s[nt][1] = __expf(s[nt][1] - mx0); sum0 += s[nt][1];
        s[nt][2] = __expf(s[nt][2] - mx1); sum1 += s[nt][2];
        s[nt][3] = __expf(s[nt][3] - mx1); sum1 += s[nt][3];
    }
    sum0 += __shfl_xor_sync(0xffffffffu, sum0, 1);
    sum0 += __shfl_xor_sync(0xffffffffu, sum0, 2);
    sum1 += __shfl_xor_sync(0xffffffffu, sum1, 1);
    sum1 += __shfl_xor_sync(0xffffffffu, sum1, 2);
    const float inv0 = 1.f / sum0;
    const float inv1 = 1.f / sum1;

    // ----- O = P V (P -> fp16 frags), key blocks kk < wid+1 -----
    float o[16][4];
#pragma unroll
    for (int nt = 0; nt < 16; nt++)
#pragma unroll
        for (int e = 0; e < 4; e++) o[nt][e] = 0.f;

    const int kmax = wid + 1;
    for (int kk = 0; kk < kmax; kk++) {
        uint32_t aP[4];
        aP[0] = pkh2(__float2half_rn(s[2 * kk][0]),     __float2half_rn(s[2 * kk][1]));
        aP[1] = pkh2(__float2half_rn(s[2 * kk][2]),     __float2half_rn(s[2 * kk][3]));
        aP[2] = pkh2(__float2half_rn(s[2 * kk + 1][0]), __float2half_rn(s[2 * kk + 1][1]));
        aP[3] = pkh2(__float2half_rn(s[2 * kk + 1][2]), __float2half_rn(s[2 * kk + 1][3]));
#pragma unroll
        for (int nt = 0; nt < 16; nt++) {
            uint32_t v[2];
            int l16  = lane & 15;
            int krow = kk * 16 + l16;
            int sw   = nt ^ (krow & 7);
            ldsm2ta(v, smem_u32(sV + krow * 128 + sw * 8));
            mma_h(o[nt], aP, v);
        }
    }

    // ----- epilogue: fp16 (input to proj GEMM) -----
    const size_t tok0 = t0 + r0;
    const size_t tok1 = t0 + r1;
#pragma unroll
    for (int nt = 0; nt < 16; nt++) {
        int col = h * DHEAD + nt * 8 + tq * 2;
        *reinterpret_cast<uint32_t*>(att + tok0 * CDIM + col) =
            pkh2(__float2half_rn(o[nt][0] * inv0), __float2half_rn(o[nt][1] * inv0));
        *reinterpret_cast<uint32_t*>(att + tok1 * CDIM + col) =
            pkh2(__float2half_rn(o[nt][2] * inv1), __float2half_rn(o[nt][3] * inv1));
    }
}

// ---------------------------------------------------------------------------
// Host launcher
// ---------------------------------------------------------------------------
extern "C" void kernel_launch(void* const* d_in, const int* in_sizes, int n_in,
                              void* d_out, int out_size) {
    const float* x  = (const float*)d_in[0];
    const float* wq = (const float*)d_in[1];
    const float* wp = (const float*)d_in[2];
    float* out = (float*)d_out;

    void *pX, *pWq, *pWp, *pQKV, *pA;
    cudaGetSymbolAddress(&pX,   g_X);
    cudaGetSymbolAddress(&pWq,  g_Wq);
    cudaGetSymbolAddress(&pWp,  g_Wp);
    cudaGetSymbolAddress(&pQKV, g_QKV);
    cudaGetSymbolAddress(&pA,   g_A);

    cudaFuncSetAttribute((const void*)gemm_fp16<true>,
                         cudaFuncAttributeMaxDynamicSharedMemorySize, G_SMEM);
    cudaFuncSetAttribute((const void*)gemm_fp16<false>,
                         cudaFuncAttributeMaxDynamicSharedMemorySize, G_SMEM);
    cudaFuncSetAttribute((const void*)attn_kernel,
                         cudaFuncAttributeMaxDynamicSharedMemorySize, 98304);

    // 1) X, Wq, Wp -> fp16 (single fused launch)
    {
        int nx = (MROWS * CDIM) / 4;          // 16,777,216
        int nq = (CDIM * N_QKV) / 4;          //  3,145,728
        int np = (CDIM * CDIM) / 4;           //  1,048,576
        int total = nx + nq + np;
        cvt_all_kernel<<<(total + 255) / 256, 256>>>(
            (const float4*)x,  (uint32_t*)pX,  nx,
            (const float4*)wq, (uint32_t*)pWq, nq,
            (const float4*)wp, (uint32_t*)pWp, np);
    }

    // 2) QKV = X @ Wq -> fp16
    {
        dim3 grid(N_QKV / 128, MROWS / 128);  // (48, 256)
        gemm_fp16<true><<<grid, 128, G_SMEM>>>(
            (const __half*)pX, (const __half*)pWq, nullptr, (__half*)pQKV,
            N_QKV, CDIM);
    }

    // 3) blocked causal attention -> fp16
    attn_kernel<<<BATCH * NBLK * NHEAD, 256, 98304>>>(
        (const __half*)pQKV, (__half*)pA);

    // 4) Y = A @ Wp -> fp32 final output
    {
        dim3 grid(CDIM / 128, MROWS / 128);   // (16, 256)
        gemm_fp16<false><<<grid, 128, G_SMEM>>>(
            (const __half*)pA, (const __half*)pWp, out, nullptr, CDIM, CDIM);
    }
}

// round 14
// speedup vs baseline: 1.1618x; 1.0045x over previous
#include <cuda_runtime.h>
#include <cuda_bf16.h>
#include <cuda_fp16.h>
#include <cstdint>
#include <cstddef>

// ---------------------------------------------------------------------------
// Problem constants
// ---------------------------------------------------------------------------
constexpr int BATCH = 4;
constexpr int TSEQ  = 8192;
constexpr int CDIM  = 2048;
constexpr int DHEAD = 128;
constexpr int NBLK  = 64;            // TSEQ / 128
constexpr int MROWS = BATCH * TSEQ;  // 32768
constexpr int N_QKV = 3 * CDIM;      // 6144
constexpr int NHEAD = 16;

// ---------------------------------------------------------------------------
// Static scratch (no allocations allowed)
// ---------------------------------------------------------------------------
__device__ __align__(256) __half g_X  [(size_t)MROWS * CDIM];
__device__ __align__(256) __half g_Wq [(size_t)CDIM * N_QKV];   // [K][N] native
__device__ __align__(256) __half g_Wp [(size_t)CDIM * CDIM];    // [K][N] native
__device__ __align__(256) __half g_QKV[(size_t)MROWS * N_QKV];  // fp16 intermediates
__device__ __align__(256) __half g_A  [(size_t)MROWS * CDIM];

// ---------------------------------------------------------------------------
// Helpers
// ---------------------------------------------------------------------------
__device__ __forceinline__ uint32_t smem_u32(const void* p) {
    return (uint32_t)__cvta_generic_to_shared(p);
}
__device__ __forceinline__ void cp16s(uint32_t s, const void* g) {
    asm volatile("cp.async.cg.shared.global [%0], [%1], 16;" :: "r"(s), "l"(g));
}
__device__ __forceinline__ void cp_commit() {
    asm volatile("cp.async.commit_group;");
}
template <int N>
__device__ __forceinline__ void cp_wait() {
    asm volatile("cp.async.wait_group %0;" :: "n"(N));
}

__device__ __forceinline__ uint32_t pkh2(__half a, __half b) {
    __half2 t; t.x = a; t.y = b;
    return *reinterpret_cast<uint32_t*>(&t);
}

__device__ __forceinline__ void ldsm4a(uint32_t* d, uint32_t a) {
    asm volatile("ldmatrix.sync.aligned.m8n8.x4.shared.b16 {%0,%1,%2,%3}, [%4];"
                 : "=r"(d[0]), "=r"(d[1]), "=r"(d[2]), "=r"(d[3]) : "r"(a));
}
__device__ __forceinline__ void ldsm4ta(uint32_t* d, uint32_t a) {
    asm volatile("ldmatrix.sync.aligned.m8n8.x4.trans.shared.b16 {%0,%1,%2,%3}, [%4];"
                 : "=r"(d[0]), "=r"(d[1]), "=r"(d[2]), "=r"(d[3]) : "r"(a));
}
__device__ __forceinline__ void ldsm2a(uint32_t* d, uint32_t a) {
    asm volatile("ldmatrix.sync.aligned.m8n8.x2.shared.b16 {%0,%1}, [%2];"
                 : "=r"(d[0]), "=r"(d[1]) : "r"(a));
}
__device__ __forceinline__ void ldsm2ta(uint32_t* d, uint32_t a) {
    asm volatile("ldmatrix.sync.aligned.m8n8.x2.trans.shared.b16 {%0,%1}, [%2];"
                 : "=r"(d[0]), "=r"(d[1]) : "r"(a));
}
// fp16 mma
__device__ __forceinline__ void mma_h(float* c, const uint32_t* a, const uint32_t* b) {
    asm volatile(
        "mma.sync.aligned.m16n8k16.row.col.f32.f16.f16.f32 "
        "{%0,%1,%2,%3}, {%4,%5,%6,%7}, {%8,%9}, {%0,%1,%2,%3};"
        : "+f"(c[0]), "+f"(c[1]), "+f"(c[2]), "+f"(c[3])
        : "r"(a[0]), "r"(a[1]), "r"(a[2]), "r"(a[3]), "r"(b[0]), "r"(b[1]));
}

// ---------------------------------------------------------------------------
// Fused fp32 -> fp16 (single, RN) for X, Wq, Wp in one launch
// ---------------------------------------------------------------------------
__global__ void cvt_all_kernel(const float4* __restrict__ sx, uint32_t* __restrict__ dx, int nx,
                               const float4* __restrict__ sq, uint32_t* __restrict__ dq, int nq,
                               const float4* __restrict__ sp, uint32_t* __restrict__ dp, int np) {
    int i = blockIdx.x * blockDim.x + threadIdx.x;
    const float4* src; uint32_t* dst; int j;
    if (i < nx)           { src = sx; dst = dx; j = i; }
    else if (i < nx + nq) { src = sq; dst = dq; j = i - nx; }
    else if (i < nx + nq + np) { src = sp; dst = dp; j = i - nx - nq; }
    else return;
    float4 v = src[j];
    dst[2 * j]     = pkh2(__float2half_rn(v.x), __float2half_rn(v.y));
    dst[2 * j + 1] = pkh2(__float2half_rn(v.z), __float2half_rn(v.w));
}

// ---------------------------------------------------------------------------
// fp16 single-pass GEMM: C[M,N] = A[M,K] @ B[K,N]
// BM=128, BN=128, BK=64, 3-stage cp.async ring.
// 128 threads = 4 warps (2m x 2n), warp tile 64x64, 2 CTAs/SM.
// Register pipeline (frags for kk+1 during kk) + cp.async issues spread
// across the four kk blocks to smooth LSU pressure.  (unchanged from R13)
// ---------------------------------------------------------------------------
constexpr int G_STAGE = 32768;
constexpr int G_BOFF  = 16384;
constexpr int G_SMEM  = 3 * G_STAGE;  // 98304

template <bool OUT_HALF>
__global__ void __launch_bounds__(128, 2) gemm_fp16(
    const __half* __restrict__ A, const __half* __restrict__ B,
    float* __restrict__ Cf, __half* __restrict__ Ch, int Nn, int Kk)
{
    extern __shared__ char smem[];
    const uint32_t sbase = smem_u32(smem);
    const int tid  = threadIdx.x;
    const int lane = tid & 31;
    const int wid  = tid >> 5;
    const int m0   = blockIdx.y * 128;
    const int n0   = blockIdx.x * 128;
    const int wm   = (wid >> 1) * 64;
    const int wn   = (wid & 1) * 64;

    const int ra = tid >> 3, ca = tid & 7;
    const char* gA0 = (const char*)(A + (size_t)(m0 + ra) * Kk + ca * 8);
    const uint32_t sA0 = sbase + ra * 128 + ((ca ^ (ra & 7)) * 16);
    const size_t rowA = (size_t)16 * Kk * 2;       // +16 rows
    const int rb = tid >> 4, cb = tid & 15;
    const char* gB0 = (const char*)(B + (size_t)rb * Nn + n0 + cb * 8);
    const uint32_t sB0 = sbase + G_BOFF + rb * 256 + ((cb ^ (rb & 7)) * 16);
    const size_t rowB = (size_t)8 * Nn * 2;        // +8 krows

    const size_t stepA = 128;                      // k-tile: 64 halfs
    const size_t stepB = (size_t)64 * Nn * 2;

    const int NK = Kk / 64;

    // prologue: stages 0..1
#pragma unroll
    for (int s = 0; s < 2; s++) {
        uint32_t so = (uint32_t)(s * G_STAGE);
        const char* ga = gA0 + (size_t)s * stepA;
        const char* gb = gB0 + (size_t)s * stepB;
#pragma unroll
        for (int i = 0; i < 8; i++)
            cp16s(sA0 + so + i * (16 * 128), ga + (size_t)i * rowA);
#pragma unroll
        for (int i = 0; i < 8; i++)
            cp16s(sB0 + so + i * (8 * 256), gb + (size_t)i * rowB);
        cp_commit();
    }

    float c[4][8][4];
#pragma unroll
    for (int mt = 0; mt < 4; mt++)
#pragma unroll
        for (int nt = 0; nt < 8; nt++)
#pragma unroll
            for (int e = 0; e < 4; e++) c[mt][nt][e] = 0.f;

    uint32_t aa[2][4][4], bb[2][4][4];

    auto load_frags = [&](uint32_t sbuf, int kk, int buf) {
#pragma unroll
        for (int p = 0; p < 4; p++) {
            int krow = kk * 16 + (lane & 15);
            int ch   = (wn >> 3) + p * 2 + (lane >> 4);
            int sw   = ch ^ (krow & 7);
            ldsm4ta(bb[buf][p], sbuf + G_BOFF + krow * 256 + sw * 16);
        }
#pragma unroll
        for (int mt = 0; mt < 4; mt++) {
            int r  = wm + mt * 16 + (lane & 15);
            int ch = kk * 2 + (lane >> 4);
            int sw = ch ^ (r & 7);
            ldsm4a(aa[buf][mt], sbuf + r * 128 + sw * 16);
        }
    };

    int sidx = 0;
    for (int kt = 0; kt < NK; kt++) {
        cp_wait<1>();
        __syncthreads();

        const uint32_t sbuf = sbase + sidx * G_STAGE;
        load_frags(sbuf, 0, 0);

        const int kn = kt + 2;
        const bool dold = (kn < NK);
        int sn = sidx + 2; if (sn >= 3) sn -= 3;
        const uint32_t so = (uint32_t)(sn * G_STAGE);
        const char* ga = gA0 + (size_t)kn * stepA;
        const char* gb = gB0 + (size_t)kn * stepB;

#pragma unroll
        for (int kk = 0; kk < 4; kk++) {
            const int buf = kk & 1;
            if (kk < 3) load_frags(sbuf, kk + 1, buf ^ 1);
            if (dold) {
#pragma unroll
                for (int i = 2 * kk; i < 2 * kk + 2; i++) {
                    cp16s(sA0 + so + i * (16 * 128), ga + (size_t)i * rowA);
                    cp16s(sB0 + so + i * (8 * 256), gb + (size_t)i * rowB);
                }
            }
#pragma unroll
            for (int mt = 0; mt < 4; mt++)
#pragma unroll
                for (int p = 0; p < 4; p++) {
                    mma_h(c[mt][2 * p],     aa[buf][mt], &bb[buf][p][0]);
                    mma_h(c[mt][2 * p + 1], aa[buf][mt], &bb[buf][p][2]);
                }
        }
        cp_commit();
        sidx++; if (sidx >= 3) sidx = 0;
    }

    // epilogue
#pragma unroll
    for (int mt = 0; mt < 4; mt++) {
#pragma unroll
        for (int nt = 0; nt < 8; nt++) {
            int row = m0 + wm + mt * 16 + (lane >> 2);
            int col = n0 + wn + nt * 8 + (lane & 3) * 2;
            if (OUT_HALF) {
                *reinterpret_cast<uint32_t*>(Ch + (size_t)row * Nn + col) =
                    pkh2(__float2half_rn(c[mt][nt][0]), __float2half_rn(c[mt][nt][1]));
                *reinterpret_cast<uint32_t*>(Ch + (size_t)(row + 8) * Nn + col) =
                    pkh2(__float2half_rn(c[mt][nt][2]), __float2half_rn(c[mt][nt][3]));
            } else {
                *reinterpret_cast<float2*>(Cf + (size_t)row * Nn + col) =
                    make_float2(c[mt][nt][0], c[mt][nt][1]);
                *reinterpret_cast<float2*>(Cf + (size_t)(row + 8) * Nn + col) =
                    make_float2(c[mt][nt][2], c[mt][nt][3]);
            }
        }
    }
}

// ---------------------------------------------------------------------------
// Attention: one CTA per (b, blk, h). fp16 QKV in, single-pass fp16 mma,
// causal triangular skipping. smem: sQ/sK/sV each [128][128] fp16 = 96KB.
// SMSP load balance: warp w computes query tile qt = (w<4) ? w : 11-w, so
// SMSP s hosts tiles {s, 7-s} -> equal work (27 units) on every scheduler
// (was {s, s+4} -> 18..36, critical path 36).
// ---------------------------------------------------------------------------
__global__ void __launch_bounds__(256, 1) attn_kernel(
    const __half* __restrict__ qkv, __half* __restrict__ att)
{
    extern __shared__ char smem[];
    __half* sQ = reinterpret_cast<__half*>(smem);            // [128][128]
    __half* sK = reinterpret_cast<__half*>(smem) + 16384;
    __half* sV = reinterpret_cast<__half*>(smem) + 32768;

    const int tid  = threadIdx.x;
    const int lane = tid & 31;
    const int wid  = tid >> 5;
    const int qt   = (wid < 4) ? wid : 11 - wid;   // query tile for this warp

    const int cta = blockIdx.x;
    const int h   = cta & 15;
    const int blk = (cta >> 4) & 63;
    const int b   = cta >> 10;
    const size_t t0 = (size_t)b * TSEQ + (size_t)blk * 128;

    // load Q,K,V: 3 tensors x 128 rows x 16 chunks(16B) = 6144 tasks
#pragma unroll
    for (int t = 0; t < 24; t++) {
        int idx = tid + t * 256;
        int tensor = idx >> 11;          // 0..2
        int rem = idx & 2047;
        int r  = rem >> 4;
        int ch = rem & 15;
        const __half* g = qkv + (t0 + r) * (size_t)N_QKV
                        + tensor * CDIM + h * DHEAD + ch * 8;
        __half* dstb = (tensor == 0) ? sQ : (tensor == 1) ? sK : sV;
        cp16s(smem_u32(dstb + r * 128 + ((ch ^ (r & 7)) * 8)), g);
    }
    cp_commit();
    cp_wait<0>();
    __syncthreads();

    // ----- S = Q K^T (warp tile 16 x 128), causal-skipped -----
    const int rw0  = qt * 16;
    const int nmax = 2 * qt + 2;        // key tiles needed (n8 granularity)

    float s[16][4];
#pragma unroll
    for (int nt = 0; nt < 16; nt++)
#pragma unroll
        for (int e = 0; e < 4; e++) s[nt][e] = 0.f;

#pragma unroll
    for (int kk = 0; kk < 8; kk++) {
        uint32_t q[4];
        {
            int r  = rw0 + (lane & 15);
            int ch = kk * 2 + (lane >> 4);
            int sw = ch ^ (r & 7);
            ldsm4a(q, smem_u32(sQ + r * 128 + sw * 8));
        }
        for (int nt = 0; nt < nmax; nt++) {
            uint32_t k[2];
            int l16  = lane & 15;
            int nrow = nt * 8 + (l16 & 7);
            int ch   = kk * 2 + (l16 >> 3);
            int sw   = ch ^ (nrow & 7);
            ldsm2a(k, smem_u32(sK + nrow * 128 + sw * 8));
            mma_h(s[nt], q, k);
        }
    }

    // ----- causal softmax (over valid tiles only) -----
    const float scale = 0.08838834764831845f;  // 1/sqrt(128)
    const int g  = lane >> 2;
    const int tq = lane & 3;
    const int r0 = rw0 + g;
    const int r1 = r0 + 8;

    float mx0 = -1e30f, mx1 = -1e30f;
    for (int nt = 0; nt < nmax; nt++) {
        int j0 = nt * 8 + tq * 2;
        int j1 = j0 + 1;
        float v;
        v = s[nt][0] * scale; if (j0 > r0) v = -1e30f; s[nt][0] = v; mx0 = fmaxf(mx0, v);
        v = s[nt][1] * scale; if (j1 > r0) v = -1e30f; s[nt][1] = v; mx0 = fmaxf(mx0, v);
        v = s[nt][2] * scale; if (j0 > r1) v = -1e30f; s[nt][2] = v; mx1 = fmaxf(mx1, v);
        v = s[nt][3] * scale; if (j1 > r1) v = -1e30f; s[nt][3] = v; mx1 = fmaxf(mx1, v);
    }
    mx0 = fmaxf(mx0, __shfl_xor_sync(0xffffffffu, mx0, 1));
    mx0 = fmaxf(mx0, __shfl_xor_sync(0xffffffffu, mx0, 2));
    mx1 = fmaxf(mx1, __shfl_xor_sync(0xffffffffu, mx1, 1));
    mx1 = fmaxf(mx1, __shfl_xor_sync(0xffffffffu, mx1, 2));

    float sum0 = 0.f, sum1 = 0.f;
    for (int nt = 0; nt < nmax; nt++) {
        s[nt][0] = __expf(s[nt][0] - mx0); sum0 += s[nt][0];
        s[nt][1] = __expf(s[nt][1] - mx0); sum0 += s[nt][1];
        s[nt][2] = __expf(s[nt][2] - mx1); sum1 += s[nt][2];
        s[nt][3] = __expf(s[nt][3] - mx1); sum1 += s[nt][3];
    }
    sum0 += __shfl_xor_sync(0xffffffffu, sum0, 1);
    sum0 += __shfl_xor_sync(0xffffffffu, sum0, 2);
    sum1 += __shfl_xor_sync(0xffffffffu, sum1, 1);
    sum1 += __shfl_xor_sync(0xffffffffu, sum1, 2);
    const float inv0 = 1.f / sum0;
    const float inv1 = 1.f / sum1;

    // ----- O = P V (P -> fp16 frags), key blocks kk < qt+1 -----
    float o[16][4];
#pragma unroll
    for (int nt = 0; nt < 16; nt++)
#pragma unroll
        for (int e = 0; e < 4; e++) o[nt][e] = 0.f;

    const int kmax = qt + 1;
    for (int kk = 0; kk < kmax; kk++) {
        uint32_t aP[4];
        aP[0] = pkh2(__float2half_rn(s[2 * kk][0]),     __float2half_rn(s[2 * kk][1]));
        aP[1] = pkh2(__float2half_rn(s[2 * kk][2]),     __float2half_rn(s[2 * kk][3]));
        aP[2] = pkh2(__float2half_rn(s[2 * kk + 1][0]), __float2half_rn(s[2 * kk + 1][1]));
        aP[3] = pkh2(__float2half_rn(s[2 * kk + 1][2]), __float2half_rn(s[2 * kk + 1][3]));
#pragma unroll
        for (int nt = 0; nt < 16; nt++) {
            uint32_t v[2];
            int l16  = lane & 15;
            int krow = kk * 16 + l16;
            int sw   = nt ^ (krow & 7);
            ldsm2ta(v, smem_u32(sV + krow * 128 + sw * 8));
            mma_h(o[nt], aP, v);
        }
    }

    // ----- epilogue: fp16 (input to proj GEMM) -----
    const size_t tok0 = t0 + r0;
    const size_t tok1 = t0 + r1;
#pragma unroll
    for (int nt = 0; nt < 16; nt++) {
        int col = h * DHEAD + nt * 8 + tq * 2;
        *reinterpret_cast<uint32_t*>(att + tok0 * CDIM + col) =
            pkh2(__float2half_rn(o[nt][0] * inv0), __float2half_rn(o[nt][1] * inv0));
        *reinterpret_cast<uint32_t*>(att + tok1 * CDIM + col) =
            pkh2(__float2half_rn(o[nt][2] * inv1), __float2half_rn(o[nt][3] * inv1));
    }
}

// ---------------------------------------------------------------------------
// Host launcher
// ---------------------------------------------------------------------------
extern "C" void kernel_launch(void* const* d_in, const int* in_sizes, int n_in,
                              void* d_out, int out_size) {
    const float* x  = (const float*)d_in[0];
    const float* wq = (const float*)d_in[1];
    const float* wp = (const float*)d_in[2];
    float* out = (float*)d_out;

    void *pX, *pWq, *pWp, *pQKV, *pA;
    cudaGetSymbolAddress(&pX,   g_X);
    cudaGetSymbolAddress(&pWq,  g_Wq);
    cudaGetSymbolAddress(&pWp,  g_Wp);
    cudaGetSymbolAddress(&pQKV, g_QKV);
    cudaGetSymbolAddress(&pA,   g_A);

    cudaFuncSetAttribute((const void*)gemm_fp16<true>,
                         cudaFuncAttributeMaxDynamicSharedMemorySize, G_SMEM);
    cudaFuncSetAttribute((const void*)gemm_fp16<false>,
                         cudaFuncAttributeMaxDynamicSharedMemorySize, G_SMEM);
    cudaFuncSetAttribute((const void*)attn_kernel,
                         cudaFuncAttributeMaxDynamicSharedMemorySize, 98304);

    // 1) X, Wq, Wp -> fp16 (single fused launch)
    {
        int nx = (MROWS * CDIM) / 4;          // 16,777,216
        int nq = (CDIM * N_QKV) / 4;          //  3,145,728
        int np = (CDIM * CDIM) / 4;           //  1,048,576
        int total = nx + nq + np;
        cvt_all_kernel<<<(total + 255) / 256, 256>>>(
            (const float4*)x,  (uint32_t*)pX,  nx,
            (const float4*)wq, (uint32_t*)pWq, nq,
            (const float4*)wp, (uint32_t*)pWp, np);
    }

    // 2) QKV = X @ Wq -> fp16
    {
        dim3 grid(N_QKV / 128, MROWS / 128);  // (48, 256)
        gemm_fp16<true><<<grid, 128, G_SMEM>>>(
            (const __half*)pX, (const __half*)pWq, nullptr, (__half*)pQKV,
            N_QKV, CDIM);
    }

    // 3) blocked causal attention -> fp16
    attn_kernel<<<BATCH * NBLK * NHEAD, 256, 98304>>>(
        (const __half*)pQKV, (__half*)pA);

    // 4) Y = A @ Wp -> fp32 final output
    {
        dim3 grid(CDIM / 128, MROWS / 128);   // (16, 256)
        gemm_fp16<false><<<grid, 128, G_SMEM>>>(
            (const __half*)pA, (const __half*)pWp, out, nullptr, CDIM, CDIM);
    }
}

// round 15
// speedup vs baseline: 1.1649x; 1.0026x over previous
#include <cuda_runtime.h>
#include <cuda_bf16.h>
#include <cuda_fp16.h>
#include <cstdint>
#include <cstddef>

// ---------------------------------------------------------------------------
// Problem constants
// ---------------------------------------------------------------------------
constexpr int BATCH = 4;
constexpr int TSEQ  = 8192;
constexpr int CDIM  = 2048;
constexpr int DHEAD = 128;
constexpr int NBLK  = 64;            // TSEQ / 128
constexpr int MROWS = BATCH * TSEQ;  // 32768
constexpr int N_QKV = 3 * CDIM;      // 6144
constexpr int NHEAD = 16;

// ---------------------------------------------------------------------------
// Static scratch (no allocations allowed)
// ---------------------------------------------------------------------------
__device__ __align__(256) __half g_X  [(size_t)MROWS * CDIM];
__device__ __align__(256) __half g_Wq [(size_t)CDIM * N_QKV];   // [K][N] native
__device__ __align__(256) __half g_Wp [(size_t)CDIM * CDIM];    // [K][N] native
__device__ __align__(256) __half g_QKV[(size_t)MROWS * N_QKV];  // fp16 intermediates
__device__ __align__(256) __half g_A  [(size_t)MROWS * CDIM];

// ---------------------------------------------------------------------------
// Helpers
// ---------------------------------------------------------------------------
__device__ __forceinline__ uint32_t smem_u32(const void* p) {
    return (uint32_t)__cvta_generic_to_shared(p);
}
__device__ __forceinline__ void cp16s(uint32_t s, const void* g) {
    asm volatile("cp.async.cg.shared.global [%0], [%1], 16;" :: "r"(s), "l"(g));
}
__device__ __forceinline__ void cp_commit() {
    asm volatile("cp.async.commit_group;");
}
template <int N>
__device__ __forceinline__ void cp_wait() {
    asm volatile("cp.async.wait_group %0;" :: "n"(N));
}

__device__ __forceinline__ uint32_t pkh2(__half a, __half b) {
    __half2 t; t.x = a; t.y = b;
    return *reinterpret_cast<uint32_t*>(&t);
}

__device__ __forceinline__ void ldsm4a(uint32_t* d, uint32_t a) {
    asm volatile("ldmatrix.sync.aligned.m8n8.x4.shared.b16 {%0,%1,%2,%3}, [%4];"
                 : "=r"(d[0]), "=r"(d[1]), "=r"(d[2]), "=r"(d[3]) : "r"(a));
}
__device__ __forceinline__ void ldsm4ta(uint32_t* d, uint32_t a) {
    asm volatile("ldmatrix.sync.aligned.m8n8.x4.trans.shared.b16 {%0,%1,%2,%3}, [%4];"
                 : "=r"(d[0]), "=r"(d[1]), "=r"(d[2]), "=r"(d[3]) : "r"(a));
}
__device__ __forceinline__ void ldsm2a(uint32_t* d, uint32_t a) {
    asm volatile("ldmatrix.sync.aligned.m8n8.x2.shared.b16 {%0,%1}, [%2];"
                 : "=r"(d[0]), "=r"(d[1]) : "r"(a));
}
__device__ __forceinline__ void ldsm2ta(uint32_t* d, uint32_t a) {
    asm volatile("ldmatrix.sync.aligned.m8n8.x2.trans.shared.b16 {%0,%1}, [%2];"
                 : "=r"(d[0]), "=r"(d[1]) : "r"(a));
}
// fp16 mma
__device__ __forceinline__ void mma_h(float* c, const uint32_t* a, const uint32_t* b) {
    asm volatile(
        "mma.sync.aligned.m16n8k16.row.col.f32.f16.f16.f32 "
        "{%0,%1,%2,%3}, {%4,%5,%6,%7}, {%8,%9}, {%0,%1,%2,%3};"
        : "+f"(c[0]), "+f"(c[1]), "+f"(c[2]), "+f"(c[3])
        : "r"(a[0]), "r"(a[1]), "r"(a[2]), "r"(a[3]), "r"(b[0]), "r"(b[1]));
}

// ---------------------------------------------------------------------------
// Fused fp32 -> fp16 (single, RN) for X, Wq, Wp in one launch
// ---------------------------------------------------------------------------
__global__ void cvt_all_kernel(const float4* __restrict__ sx, uint32_t* __restrict__ dx, int nx,
                               const float4* __restrict__ sq, uint32_t* __restrict__ dq, int nq,
                               const float4* __restrict__ sp, uint32_t* __restrict__ dp, int np) {
    int i = blockIdx.x * blockDim.x + threadIdx.x;
    const float4* src; uint32_t* dst; int j;
    if (i < nx)           { src = sx; dst = dx; j = i; }
    else if (i < nx + nq) { src = sq; dst = dq; j = i - nx; }
    else if (i < nx + nq + np) { src = sp; dst = dp; j = i - nx - nq; }
    else return;
    float4 v = src[j];
    dst[2 * j]     = pkh2(__float2half_rn(v.x), __float2half_rn(v.y));
    dst[2 * j + 1] = pkh2(__float2half_rn(v.z), __float2half_rn(v.w));
}

// ---------------------------------------------------------------------------
// fp16 single-pass GEMM: C[M,N] = A[M,K] @ B[K,N]
// BM=128, BN=128, BK=64, 3-stage cp.async ring.
// 128 threads = 4 warps (2m x 2n), warp tile 64x64, 2 CTAs/SM.
// Register pipeline (frags for kk+1 during kk) + cp.async issues spread
// across the four kk blocks to smooth LSU pressure.  (unchanged from R13)
// ---------------------------------------------------------------------------
constexpr int G_STAGE = 32768;
constexpr int G_BOFF  = 16384;
constexpr int G_SMEM  = 3 * G_STAGE;  // 98304

template <bool OUT_HALF>
__global__ void __launch_bounds__(128, 2) gemm_fp16(
    const __half* __restrict__ A, const __half* __restrict__ B,
    float* __restrict__ Cf, __half* __restrict__ Ch, int Nn, int Kk)
{
    extern __shared__ char smem[];
    const uint32_t sbase = smem_u32(smem);
    const int tid  = threadIdx.x;
    const int lane = tid & 31;
    const int wid  = tid >> 5;
    const int m0   = blockIdx.y * 128;
    const int n0   = blockIdx.x * 128;
    const int wm   = (wid >> 1) * 64;
    const int wn   = (wid & 1) * 64;

    const int ra = tid >> 3, ca = tid & 7;
    const char* gA0 = (const char*)(A + (size_t)(m0 + ra) * Kk + ca * 8);
    const uint32_t sA0 = sbase + ra * 128 + ((ca ^ (ra & 7)) * 16);
    const size_t rowA = (size_t)16 * Kk * 2;       // +16 rows
    const int rb = tid >> 4, cb = tid & 15;
    const char* gB0 = (const char*)(B + (size_t)rb * Nn + n0 + cb * 8);
    const uint32_t sB0 = sbase + G_BOFF + rb * 256 + ((cb ^ (rb & 7)) * 16);
    const size_t rowB = (size_t)8 * Nn * 2;        // +8 krows

    const size_t stepA = 128;                      // k-tile: 64 halfs
    const size_t stepB = (size_t)64 * Nn * 2;

    const int NK = Kk / 64;

    // prologue: stages 0..1
#pragma unroll
    for (int s = 0; s < 2; s++) {
        uint32_t so = (uint32_t)(s * G_STAGE);
        const char* ga = gA0 + (size_t)s * stepA;
        const char* gb = gB0 + (size_t)s * stepB;
#pragma unroll
        for (int i = 0; i < 8; i++)
            cp16s(sA0 + so + i * (16 * 128), ga + (size_t)i * rowA);
#pragma unroll
        for (int i = 0; i < 8; i++)
            cp16s(sB0 + so + i * (8 * 256), gb + (size_t)i * rowB);
        cp_commit();
    }

    float c[4][8][4];
#pragma unroll
    for (int mt = 0; mt < 4; mt++)
#pragma unroll
        for (int nt = 0; nt < 8; nt++)
#pragma unroll
            for (int e = 0; e < 4; e++) c[mt][nt][e] = 0.f;

    uint32_t aa[2][4][4], bb[2][4][4];

    auto load_frags = [&](uint32_t sbuf, int kk, int buf) {
#pragma unroll
        for (int p = 0; p < 4; p++) {
            int krow = kk * 16 + (lane & 15);
            int ch   = (wn >> 3) + p * 2 + (lane >> 4);
            int sw   = ch ^ (krow & 7);
            ldsm4ta(bb[buf][p], sbuf + G_BOFF + krow * 256 + sw * 16);
        }
#pragma unroll
        for (int mt = 0; mt < 4; mt++) {
            int r  = wm + mt * 16 + (lane & 15);
            int ch = kk * 2 + (lane >> 4);
            int sw = ch ^ (r & 7);
            ldsm4a(aa[buf][mt], sbuf + r * 128 + sw * 16);
        }
    };

    int sidx = 0;
    for (int kt = 0; kt < NK; kt++) {
        cp_wait<1>();
        __syncthreads();

        const uint32_t sbuf = sbase + sidx * G_STAGE;
        load_frags(sbuf, 0, 0);

        const int kn = kt + 2;
        const bool dold = (kn < NK);
        int sn = sidx + 2; if (sn >= 3) sn -= 3;
        const uint32_t so = (uint32_t)(sn * G_STAGE);
        const char* ga = gA0 + (size_t)kn * stepA;
        const char* gb = gB0 + (size_t)kn * stepB;

#pragma unroll
        for (int kk = 0; kk < 4; kk++) {
            const int buf = kk & 1;
            if (kk < 3) load_frags(sbuf, kk + 1, buf ^ 1);
            if (dold) {
#pragma unroll
                for (int i = 2 * kk; i < 2 * kk + 2; i++) {
                    cp16s(sA0 + so + i * (16 * 128), ga + (size_t)i * rowA);
                    cp16s(sB0 + so + i * (8 * 256), gb + (size_t)i * rowB);
                }
            }
#pragma unroll
            for (int mt = 0; mt < 4; mt++)
#pragma unroll
                for (int p = 0; p < 4; p++) {
                    mma_h(c[mt][2 * p],     aa[buf][mt], &bb[buf][p][0]);
                    mma_h(c[mt][2 * p + 1], aa[buf][mt], &bb[buf][p][2]);
                }
        }
        cp_commit();
        sidx++; if (sidx >= 3) sidx = 0;
    }

    // epilogue
#pragma unroll
    for (int mt = 0; mt < 4; mt++) {
#pragma unroll
        for (int nt = 0; nt < 8; nt++) {
            int row = m0 + wm + mt * 16 + (lane >> 2);
            int col = n0 + wn + nt * 8 + (lane & 3) * 2;
            if (OUT_HALF) {
                *reinterpret_cast<uint32_t*>(Ch + (size_t)row * Nn + col) =
                    pkh2(__float2half_rn(c[mt][nt][0]), __float2half_rn(c[mt][nt][1]));
                *reinterpret_cast<uint32_t*>(Ch + (size_t)(row + 8) * Nn + col) =
                    pkh2(__float2half_rn(c[mt][nt][2]), __float2half_rn(c[mt][nt][3]));
            } else {
                *reinterpret_cast<float2*>(Cf + (size_t)row * Nn + col) =
                    make_float2(c[mt][nt][0], c[mt][nt][1]);
                *reinterpret_cast<float2*>(Cf + (size_t)(row + 8) * Nn + col) =
                    make_float2(c[mt][nt][2], c[mt][nt][3]);
            }
        }
    }
}

// ---------------------------------------------------------------------------
// Attention: one CTA per (b, blk, h). fp16 QKV in, single-pass fp16 mma,
// causal triangular skipping. smem: sQ/sK/sV each [128][128] fp16 = 96KB.
// Q+K committed first, V in a second group: V's load latency is hidden
// under the whole QK^T + softmax phase.
// SMSP balance: warp w computes query tile qt = (w<4) ? w : 11-w.
// ---------------------------------------------------------------------------
__global__ void __launch_bounds__(256, 1) attn_kernel(
    const __half* __restrict__ qkv, __half* __restrict__ att)
{
    extern __shared__ char smem[];
    __half* sQ = reinterpret_cast<__half*>(smem);            // [128][128]
    __half* sK = reinterpret_cast<__half*>(smem) + 16384;
    __half* sV = reinterpret_cast<__half*>(smem) + 32768;

    const int tid  = threadIdx.x;
    const int lane = tid & 31;
    const int wid  = tid >> 5;
    const int qt   = (wid < 4) ? wid : 11 - wid;   // query tile for this warp

    const int cta = blockIdx.x;
    const int h   = cta & 15;
    const int blk = (cta >> 4) & 63;
    const int b   = cta >> 10;
    const size_t t0 = (size_t)b * TSEQ + (size_t)blk * 128;

    // Q + K: 2 tensors x 128 rows x 16 chunks(16B) = 4096 tasks -> group 1
#pragma unroll
    for (int t = 0; t < 16; t++) {
        int idx = tid + t * 256;
        int tensor = idx >> 11;          // 0..1
        int rem = idx & 2047;
        int r  = rem >> 4;
        int ch = rem & 15;
        const __half* g = qkv + (t0 + r) * (size_t)N_QKV
                        + tensor * CDIM + h * DHEAD + ch * 8;
        __half* dstb = (tensor == 0) ? sQ : sK;
        cp16s(smem_u32(dstb + r * 128 + ((ch ^ (r & 7)) * 8)), g);
    }
    cp_commit();
    // V: 128 rows x 16 chunks = 2048 tasks -> group 2 (overlaps QK^T below)
#pragma unroll
    for (int t = 0; t < 8; t++) {
        int idx = tid + t * 256;
        int r  = idx >> 4;
        int ch = idx & 15;
        const __half* g = qkv + (t0 + r) * (size_t)N_QKV
                        + 2 * CDIM + h * DHEAD + ch * 8;
        cp16s(smem_u32(sV + r * 128 + ((ch ^ (r & 7)) * 8)), g);
    }
    cp_commit();

    cp_wait<1>();    // Q, K ready (V still in flight)
    __syncthreads();

    // ----- S = Q K^T (warp tile 16 x 128), causal-skipped -----
    const int rw0  = qt * 16;
    const int nmax = 2 * qt + 2;        // key tiles needed (n8 granularity)

    float s[16][4];
#pragma unroll
    for (int nt = 0; nt < 16; nt++)
#pragma unroll
        for (int e = 0; e < 4; e++) s[nt][e] = 0.f;

#pragma unroll
    for (int kk = 0; kk < 8; kk++) {
        uint32_t q[4];
        {
            int r  = rw0 + (lane & 15);
            int ch = kk * 2 + (lane >> 4);
            int sw = ch ^ (r & 7);
            ldsm4a(q, smem_u32(sQ + r * 128 + sw * 8));
        }
        for (int nt = 0; nt < nmax; nt++) {
            uint32_t k[2];
            int l16  = lane & 15;
            int nrow = nt * 8 + (l16 & 7);
            int ch   = kk * 2 + (l16 >> 3);
            int sw   = ch ^ (nrow & 7);
            ldsm2a(k, smem_u32(sK + nrow * 128 + sw * 8));
            mma_h(s[nt], q, k);
        }
    }

    // ----- causal softmax (over valid tiles only) -----
    const float scale = 0.08838834764831845f;  // 1/sqrt(128)
    const int g  = lane >> 2;
    const int tq = lane & 3;
    const int r0 = rw0 + g;
    const int r1 = r0 + 8;

    float mx0 = -1e30f, mx1 = -1e30f;
    for (int nt = 0; nt < nmax; nt++) {
        int j0 = nt * 8 + tq * 2;
        int j1 = j0 + 1;
        float v;
        v = s[nt][0] * scale; if (j0 > r0) v = -1e30f; s[nt][0] = v; mx0 = fmaxf(mx0, v);
        v = s[nt][1] * scale; if (j1 > r0) v = -1e30f; s[nt][1] = v; mx0 = fmaxf(mx0, v);
        v = s[nt][2] * scale; if (j0 > r1) v = -1e30f; s[nt][2] = v; mx1 = fmaxf(mx1, v);
        v = s[nt][3] * scale; if (j1 > r1) v = -1e30f; s[nt][3] = v; mx1 = fmaxf(mx1, v);
    }
    mx0 = fmaxf(mx0, __shfl_xor_sync(0xffffffffu, mx0, 1));
    mx0 = fmaxf(mx0, __shfl_xor_sync(0xffffffffu, mx0, 2));
    mx1 = fmaxf(mx1, __shfl_xor_sync(0xffffffffu, mx1, 1));
    mx1 = fmaxf(mx1, __shfl_xor_sync(0xffffffffu, mx1, 2));

    float sum0 = 0.f, sum1 = 0.f;
    for (int nt = 0; nt < nmax; nt++) {
        s[nt][0] = __expf(s[nt][0] - mx0); sum0 += s[nt][0];
        s[nt][1] = __expf(s[nt][1] - mx0); sum0 += s[nt][1];
        s[nt][2] = __expf(s[nt][2] - mx1); sum1 += s[nt][2];
        s[nt][3] = __expf(s[nt][3] - mx1); sum1 += s[nt][3];
    }
    sum0 += __shfl_xor_sync(0xffffffffu, sum0, 1);
    sum0 += __shfl_xor_sync(0xffffffffu, sum0, 2);
    sum1 += __shfl_xor_sync(0xffffffffu, sum1, 1);
    sum1 += __shfl_xor_sync(0xffffffffu, sum1, 2);
    const float inv0 = 1.f / sum0;
    const float inv1 = 1.f / sum1;

    cp_wait<0>();    // V ready
    __syncthreads();

    // ----- O = P V (P -> fp16 frags), key blocks kk < qt+1 -----
    float o[16][4];
#pragma unroll
    for (int nt = 0; nt < 16; nt++)
#pragma unroll
        for (int e = 0; e < 4; e++) o[nt][e] = 0.f;

    const int kmax = qt + 1;
    for (int kk = 0; kk < kmax; kk++) {
        uint32_t aP[4];
        aP[0] = pkh2(__float2half_rn(s[2 * kk][0]),     __float2half_rn(s[2 * kk][1]));
        aP[1] = pkh2(__float2half_rn(s[2 * kk][2]),     __float2half_rn(s[2 * kk][3]));
        aP[2] = pkh2(__float2half_rn(s[2 * kk + 1][0]), __float2half_rn(s[2 * kk + 1][1]));
        aP[3] = pkh2(__float2half_rn(s[2 * kk + 1][2]), __float2half_rn(s[2 * kk + 1][3]));
#pragma unroll
        for (int nt = 0; nt < 16; nt++) {
            uint32_t v[2];
            int l16  = lane & 15;
            int krow = kk * 16 + l16;
            int sw   = nt ^ (krow & 7);
            ldsm2ta(v, smem_u32(sV + krow * 128 + sw * 8));
            mma_h(o[nt], aP, v);
        }
    }

    // ----- epilogue: fp16 (input to proj GEMM) -----
    const size_t tok0 = t0 + r0;
    const size_t tok1 = t0 + r1;
#pragma unroll
    for (int nt = 0; nt < 16; nt++) {
        int col = h * DHEAD + nt * 8 + tq * 2;
        *reinterpret_cast<uint32_t*>(att + tok0 * CDIM + col) =
            pkh2(__float2half_rn(o[nt][0] * inv0), __float2half_rn(o[nt][1] * inv0));
        *reinterpret_cast<uint32_t*>(att + tok1 * CDIM + col) =
            pkh2(__float2half_rn(o[nt][2] * inv1), __float2half_rn(o[nt][3] * inv1));
    }
}

// ---------------------------------------------------------------------------
// Host launcher
// ---------------------------------------------------------------------------
extern "C" void kernel_launch(void* const* d_in, const int* in_sizes, int n_in,
                              void* d_out, int out_size) {
    const float* x  = (const float*)d_in[0];
    const float* wq = (const float*)d_in[1];
    const float* wp = (const float*)d_in[2];
    float* out = (float*)d_out;

    void *pX, *pWq, *pWp, *pQKV, *pA;
    cudaGetSymbolAddress(&pX,   g_X);
    cudaGetSymbolAddress(&pWq,  g_Wq);
    cudaGetSymbolAddress(&pWp,  g_Wp);
    cudaGetSymbolAddress(&pQKV, g_QKV);
    cudaGetSymbolAddress(&pA,   g_A);

    cudaFuncSetAttribute((const void*)gemm_fp16<true>,
                         cudaFuncAttributeMaxDynamicSharedMemorySize, G_SMEM);
    cudaFuncSetAttribute((const void*)gemm_fp16<false>,
                         cudaFuncAttributeMaxDynamicSharedMemorySize, G_SMEM);
    cudaFuncSetAttribute((const void*)attn_kernel,
                         cudaFuncAttributeMaxDynamicSharedMemorySize, 98304);

    // 1) X, Wq, Wp -> fp16 (single fused launch)
    {
        int nx = (MROWS * CDIM) / 4;          // 16,777,216
        int nq = (CDIM * N_QKV) / 4;          //  3,145,728
        int np = (CDIM * CDIM) / 4;           //  1,048,576
        int total = nx + nq + np;
        cvt_all_kernel<<<(total + 255) / 256, 256>>>(
            (const float4*)x,  (uint32_t*)pX,  nx,
            (const float4*)wq, (uint32_t*)pWq, nq,
            (const float4*)wp, (uint32_t*)pWp, np);
    }

    // 2) QKV = X @ Wq -> fp16
    {
        dim3 grid(N_QKV / 128, MROWS / 128);  // (48, 256)
        gemm_fp16<true><<<grid, 128, G_SMEM>>>(
            (const __half*)pX, (const __half*)pWq, nullptr, (__half*)pQKV,
            N_QKV, CDIM);
    }

    // 3) blocked causal attention -> fp16
    attn_kernel<<<BATCH * NBLK * NHEAD, 256, 98304>>>(
        (const __half*)pQKV, (__half*)pA);

    // 4) Y = A @ Wp -> fp32 final output
    {
        dim3 grid(CDIM / 128, MROWS / 128);   // (16, 256)
        gemm_fp16<false><<<grid, 128, G_SMEM>>>(
            (const __half*)pA, (const __half*)pWp, out, nullptr, CDIM, CDIM);
    }
}

// round 16
// speedup vs baseline: 1.2150x; 1.0430x over previous
#include <cuda_runtime.h>
#include <cuda_bf16.h>
#include <cuda_fp16.h>
#include <cstdint>
#include <cstddef>

// ---------------------------------------------------------------------------
// Problem constants
// ---------------------------------------------------------------------------
constexpr int BATCH = 4;
constexpr int TSEQ  = 8192;
constexpr int CDIM  = 2048;
constexpr int DHEAD = 128;
constexpr int NBLK  = 64;            // TSEQ / 128
constexpr int MROWS = BATCH * TSEQ;  // 32768
constexpr int N_QKV = 3 * CDIM;      // 6144
constexpr int NHEAD = 16;

// ---------------------------------------------------------------------------
// Static scratch (no allocations allowed)
// ---------------------------------------------------------------------------
__device__ __align__(256) __half g_X  [(size_t)MROWS * CDIM];
__device__ __align__(256) __half g_Wq [(size_t)CDIM * N_QKV];   // [K][N] native
__device__ __align__(256) __half g_Wp [(size_t)CDIM * CDIM];    // [K][N] native
__device__ __align__(256) __half g_QKV[(size_t)MROWS * N_QKV];  // fp16 intermediates
__device__ __align__(256) __half g_A  [(size_t)MROWS * CDIM];

// ---------------------------------------------------------------------------
// Helpers
// ---------------------------------------------------------------------------
__device__ __forceinline__ uint32_t smem_u32(const void* p) {
    return (uint32_t)__cvta_generic_to_shared(p);
}
__device__ __forceinline__ void cp16s(uint32_t s, const void* g) {
    asm volatile("cp.async.cg.shared.global [%0], [%1], 16;" :: "r"(s), "l"(g));
}
__device__ __forceinline__ void cp_commit() {
    asm volatile("cp.async.commit_group;");
}
template <int N>
__device__ __forceinline__ void cp_wait() {
    asm volatile("cp.async.wait_group %0;" :: "n"(N));
}

__device__ __forceinline__ uint32_t pkh2(__half a, __half b) {
    __half2 t; t.x = a; t.y = b;
    return *reinterpret_cast<uint32_t*>(&t);
}

__device__ __forceinline__ void ldsm4a(uint32_t* d, uint32_t a) {
    asm volatile("ldmatrix.sync.aligned.m8n8.x4.shared.b16 {%0,%1,%2,%3}, [%4];"
                 : "=r"(d[0]), "=r"(d[1]), "=r"(d[2]), "=r"(d[3]) : "r"(a));
}
__device__ __forceinline__ void ldsm4ta(uint32_t* d, uint32_t a) {
    asm volatile("ldmatrix.sync.aligned.m8n8.x4.trans.shared.b16 {%0,%1,%2,%3}, [%4];"
                 : "=r"(d[0]), "=r"(d[1]), "=r"(d[2]), "=r"(d[3]) : "r"(a));
}
__device__ __forceinline__ void ldsm2a(uint32_t* d, uint32_t a) {
    asm volatile("ldmatrix.sync.aligned.m8n8.x2.shared.b16 {%0,%1}, [%2];"
                 : "=r"(d[0]), "=r"(d[1]) : "r"(a));
}
__device__ __forceinline__ void ldsm2ta(uint32_t* d, uint32_t a) {
    asm volatile("ldmatrix.sync.aligned.m8n8.x2.trans.shared.b16 {%0,%1}, [%2];"
                 : "=r"(d[0]), "=r"(d[1]) : "r"(a));
}
// fp16 mma
__device__ __forceinline__ void mma_h(float* c, const uint32_t* a, const uint32_t* b) {
    asm volatile(
        "mma.sync.aligned.m16n8k16.row.col.f32.f16.f16.f32 "
        "{%0,%1,%2,%3}, {%4,%5,%6,%7}, {%8,%9}, {%0,%1,%2,%3};"
        : "+f"(c[0]), "+f"(c[1]), "+f"(c[2]), "+f"(c[3])
        : "r"(a[0]), "r"(a[1]), "r"(a[2]), "r"(a[3]), "r"(b[0]), "r"(b[1]));
}

// ---------------------------------------------------------------------------
// Fused fp32 -> fp16 (single, RN) for X, Wq, Wp in one launch
// ---------------------------------------------------------------------------
__global__ void cvt_all_kernel(const float4* __restrict__ sx, uint32_t* __restrict__ dx, int nx,
                               const float4* __restrict__ sq, uint32_t* __restrict__ dq, int nq,
                               const float4* __restrict__ sp, uint32_t* __restrict__ dp, int np) {
    int i = blockIdx.x * blockDim.x + threadIdx.x;
    const float4* src; uint32_t* dst; int j;
    if (i < nx)           { src = sx; dst = dx; j = i; }
    else if (i < nx + nq) { src = sq; dst = dq; j = i - nx; }
    else if (i < nx + nq + np) { src = sp; dst = dp; j = i - nx - nq; }
    else return;
    float4 v = src[j];
    dst[2 * j]     = pkh2(__float2half_rn(v.x), __float2half_rn(v.y));
    dst[2 * j + 1] = pkh2(__float2half_rn(v.z), __float2half_rn(v.w));
}

// ---------------------------------------------------------------------------
// fp16 single-pass GEMM: C[M,N] = A[M,K] @ B[K,N]
// BM=128, BN=128, BK=64, 3-stage cp.async ring.
// 128 threads = 4 warps (2m x 2n), warp tile 64x64, 2 CTAs/SM.
// Register pipeline (frags for kk+1 during kk) + cp.async issues spread
// across the four kk blocks to smooth LSU pressure.  (unchanged from R13)
// ---------------------------------------------------------------------------
constexpr int G_STAGE = 32768;
constexpr int G_BOFF  = 16384;
constexpr int G_SMEM  = 3 * G_STAGE;  // 98304

template <bool OUT_HALF>
__global__ void __launch_bounds__(128, 2) gemm_fp16(
    const __half* __restrict__ A, const __half* __restrict__ B,
    float* __restrict__ Cf, __half* __restrict__ Ch, int Nn, int Kk)
{
    extern __shared__ char smem[];
    const uint32_t sbase = smem_u32(smem);
    const int tid  = threadIdx.x;
    const int lane = tid & 31;
    const int wid  = tid >> 5;
    const int m0   = blockIdx.y * 128;
    const int n0   = blockIdx.x * 128;
    const int wm   = (wid >> 1) * 64;
    const int wn   = (wid & 1) * 64;

    const int ra = tid >> 3, ca = tid & 7;
    const char* gA0 = (const char*)(A + (size_t)(m0 + ra) * Kk + ca * 8);
    const uint32_t sA0 = sbase + ra * 128 + ((ca ^ (ra & 7)) * 16);
    const size_t rowA = (size_t)16 * Kk * 2;       // +16 rows
    const int rb = tid >> 4, cb = tid & 15;
    const char* gB0 = (const char*)(B + (size_t)rb * Nn + n0 + cb * 8);
    const uint32_t sB0 = sbase + G_BOFF + rb * 256 + ((cb ^ (rb & 7)) * 16);
    const size_t rowB = (size_t)8 * Nn * 2;        // +8 krows

    const size_t stepA = 128;                      // k-tile: 64 halfs
    const size_t stepB = (size_t)64 * Nn * 2;

    const int NK = Kk / 64;

    // prologue: stages 0..1
#pragma unroll
    for (int s = 0; s < 2; s++) {
        uint32_t so = (uint32_t)(s * G_STAGE);
        const char* ga = gA0 + (size_t)s * stepA;
        const char* gb = gB0 + (size_t)s * stepB;
#pragma unroll
        for (int i = 0; i < 8; i++)
            cp16s(sA0 + so + i * (16 * 128), ga + (size_t)i * rowA);
#pragma unroll
        for (int i = 0; i < 8; i++)
            cp16s(sB0 + so + i * (8 * 256), gb + (size_t)i * rowB);
        cp_commit();
    }

    float c[4][8][4];
#pragma unroll
    for (int mt = 0; mt < 4; mt++)
#pragma unroll
        for (int nt = 0; nt < 8; nt++)
#pragma unroll
            for (int e = 0; e < 4; e++) c[mt][nt][e] = 0.f;

    uint32_t aa[2][4][4], bb[2][4][4];

    auto load_frags = [&](uint32_t sbuf, int kk, int buf) {
#pragma unroll
        for (int p = 0; p < 4; p++) {
            int krow = kk * 16 + (lane & 15);
            int ch   = (wn >> 3) + p * 2 + (lane >> 4);
            int sw   = ch ^ (krow & 7);
            ldsm4ta(bb[buf][p], sbuf + G_BOFF + krow * 256 + sw * 16);
        }
#pragma unroll
        for (int mt = 0; mt < 4; mt++) {
            int r  = wm + mt * 16 + (lane & 15);
            int ch = kk * 2 + (lane >> 4);
            int sw = ch ^ (r & 7);
            ldsm4a(aa[buf][mt], sbuf + r * 128 + sw * 16);
        }
    };

    int sidx = 0;
    for (int kt = 0; kt < NK; kt++) {
        cp_wait<1>();
        __syncthreads();

        const uint32_t sbuf = sbase + sidx * G_STAGE;
        load_frags(sbuf, 0, 0);

        const int kn = kt + 2;
        const bool dold = (kn < NK);
        int sn = sidx + 2; if (sn >= 3) sn -= 3;
        const uint32_t so = (uint32_t)(sn * G_STAGE);
        const char* ga = gA0 + (size_t)kn * stepA;
        const char* gb = gB0 + (size_t)kn * stepB;

#pragma unroll
        for (int kk = 0; kk < 4; kk++) {
            const int buf = kk & 1;
            if (kk < 3) load_frags(sbuf, kk + 1, buf ^ 1);
            if (dold) {
#pragma unroll
                for (int i = 2 * kk; i < 2 * kk + 2; i++) {
                    cp16s(sA0 + so + i * (16 * 128), ga + (size_t)i * rowA);
                    cp16s(sB0 + so + i * (8 * 256), gb + (size_t)i * rowB);
                }
            }
#pragma unroll
            for (int mt = 0; mt < 4; mt++)
#pragma unroll
                for (int p = 0; p < 4; p++) {
                    mma_h(c[mt][2 * p],     aa[buf][mt], &bb[buf][p][0]);
                    mma_h(c[mt][2 * p + 1], aa[buf][mt], &bb[buf][p][2]);
                }
        }
        cp_commit();
        sidx++; if (sidx >= 3) sidx = 0;
    }

    // epilogue
#pragma unroll
    for (int mt = 0; mt < 4; mt++) {
#pragma unroll
        for (int nt = 0; nt < 8; nt++) {
            int row = m0 + wm + mt * 16 + (lane >> 2);
            int col = n0 + wn + nt * 8 + (lane & 3) * 2;
            if (OUT_HALF) {
                *reinterpret_cast<uint32_t*>(Ch + (size_t)row * Nn + col) =
                    pkh2(__float2half_rn(c[mt][nt][0]), __float2half_rn(c[mt][nt][1]));
                *reinterpret_cast<uint32_t*>(Ch + (size_t)(row + 8) * Nn + col) =
                    pkh2(__float2half_rn(c[mt][nt][2]), __float2half_rn(c[mt][nt][3]));
            } else {
                *reinterpret_cast<float2*>(Cf + (size_t)row * Nn + col) =
                    make_float2(c[mt][nt][0], c[mt][nt][1]);
                *reinterpret_cast<float2*>(Cf + (size_t)(row + 8) * Nn + col) =
                    make_float2(c[mt][nt][2], c[mt][nt][3]);
            }
        }
    }
}

// ---------------------------------------------------------------------------
// Attention: one CTA per (b, blk, h). fp16 QKV in, single-pass fp16 mma.
// Causal skipping via FULLY UNROLLED loops with predicated bodies: all
// indices into s[]/o[] are compile-time constants so the accumulators stay
// in registers (dynamic trip counts previously forced local-memory spills).
// smem: sQ/sK/sV each [128][128] fp16 = 96KB. Q+K group 1, V group 2.
// SMSP balance: warp w computes query tile qt = (w<4) ? w : 11-w.
// ---------------------------------------------------------------------------
__global__ void __launch_bounds__(256, 1) attn_kernel(
    const __half* __restrict__ qkv, __half* __restrict__ att)
{
    extern __shared__ char smem[];
    __half* sQ = reinterpret_cast<__half*>(smem);            // [128][128]
    __half* sK = reinterpret_cast<__half*>(smem) + 16384;
    __half* sV = reinterpret_cast<__half*>(smem) + 32768;

    const int tid  = threadIdx.x;
    const int lane = tid & 31;
    const int wid  = tid >> 5;
    const int qt   = (wid < 4) ? wid : 11 - wid;   // query tile for this warp

    const int cta = blockIdx.x;
    const int h   = cta & 15;
    const int blk = (cta >> 4) & 63;
    const int b   = cta >> 10;
    const size_t t0 = (size_t)b * TSEQ + (size_t)blk * 128;

    // Q + K: 2 tensors x 128 rows x 16 chunks(16B) = 4096 tasks -> group 1
#pragma unroll
    for (int t = 0; t < 16; t++) {
        int idx = tid + t * 256;
        int tensor = idx >> 11;          // 0..1
        int rem = idx & 2047;
        int r  = rem >> 4;
        int ch = rem & 15;
        const __half* g = qkv + (t0 + r) * (size_t)N_QKV
                        + tensor * CDIM + h * DHEAD + ch * 8;
        __half* dstb = (tensor == 0) ? sQ : sK;
        cp16s(smem_u32(dstb + r * 128 + ((ch ^ (r & 7)) * 8)), g);
    }
    cp_commit();
    // V: 128 rows x 16 chunks = 2048 tasks -> group 2 (overlaps QK^T below)
#pragma unroll
    for (int t = 0; t < 8; t++) {
        int idx = tid + t * 256;
        int r  = idx >> 4;
        int ch = idx & 15;
        const __half* g = qkv + (t0 + r) * (size_t)N_QKV
                        + 2 * CDIM + h * DHEAD + ch * 8;
        cp16s(smem_u32(sV + r * 128 + ((ch ^ (r & 7)) * 8)), g);
    }
    cp_commit();

    cp_wait<1>();    // Q, K ready (V still in flight)
    __syncthreads();

    // ----- S = Q K^T (warp tile 16 x 128), predicated causal skipping -----
    const int rw0  = qt * 16;
    const int nmax = 2 * qt + 2;        // key tiles needed (n8 granularity)

    float s[16][4];
#pragma unroll
    for (int nt = 0; nt < 16; nt++)
#pragma unroll
        for (int e = 0; e < 4; e++) s[nt][e] = 0.f;

#pragma unroll
    for (int kk = 0; kk < 8; kk++) {
        uint32_t q[4];
        {
            int r  = rw0 + (lane & 15);
            int ch = kk * 2 + (lane >> 4);
            int sw = ch ^ (r & 7);
            ldsm4a(q, smem_u32(sQ + r * 128 + sw * 8));
        }
#pragma unroll
        for (int nt = 0; nt < 16; nt++) {
            if (nt < nmax) {
                uint32_t k[2];
                int l16  = lane & 15;
                int nrow = nt * 8 + (l16 & 7);
                int ch   = kk * 2 + (l16 >> 3);
                int sw   = ch ^ (nrow & 7);
                ldsm2a(k, smem_u32(sK + nrow * 128 + sw * 8));
                mma_h(s[nt], q, k);
            }
        }
    }

    // ----- causal softmax (predicated over valid tiles) -----
    const float scale = 0.08838834764831845f;  // 1/sqrt(128)
    const int g  = lane >> 2;
    const int tq = lane & 3;
    const int r0 = rw0 + g;
    const int r1 = r0 + 8;

    float mx0 = -1e30f, mx1 = -1e30f;
#pragma unroll
    for (int nt = 0; nt < 16; nt++) {
        if (nt < nmax) {
            int j0 = nt * 8 + tq * 2;
            int j1 = j0 + 1;
            float v;
            v = s[nt][0] * scale; if (j0 > r0) v = -1e30f; s[nt][0] = v; mx0 = fmaxf(mx0, v);
            v = s[nt][1] * scale; if (j1 > r0) v = -1e30f; s[nt][1] = v; mx0 = fmaxf(mx0, v);
            v = s[nt][2] * scale; if (j0 > r1) v = -1e30f; s[nt][2] = v; mx1 = fmaxf(mx1, v);
            v = s[nt][3] * scale; if (j1 > r1) v = -1e30f; s[nt][3] = v; mx1 = fmaxf(mx1, v);
        }
    }
    mx0 = fmaxf(mx0, __shfl_xor_sync(0xffffffffu, mx0, 1));
    mx0 = fmaxf(mx0, __shfl_xor_sync(0xffffffffu, mx0, 2));
    mx1 = fmaxf(mx1, __shfl_xor_sync(0xffffffffu, mx1, 1));
    mx1 = fmaxf(mx1, __shfl_xor_sync(0xffffffffu, mx1, 2));

    float sum0 = 0.f, sum1 = 0.f;
#pragma unroll
    for (int nt = 0; nt < 16; nt++) {
        if (nt < nmax) {
            s[nt][0] = __expf(s[nt][0] - mx0); sum0 += s[nt][0];
            s[nt][1] = __expf(s[nt][1] - mx0); sum0 += s[nt][1];
            s[nt][2] = __expf(s[nt][2] - mx1); sum1 += s[nt][2];
            s[nt][3] = __expf(s[nt][3] - mx1); sum1 += s[nt][3];
        }
    }
    sum0 += __shfl_xor_sync(0xffffffffu, sum0, 1);
    sum0 += __shfl_xor_sync(0xffffffffu, sum0, 2);
    sum1 += __shfl_xor_sync(0xffffffffu, sum1, 1);
    sum1 += __shfl_xor_sync(0xffffffffu, sum1, 2);
    const float inv0 = 1.f / sum0;
    const float inv1 = 1.f / sum1;

    cp_wait<0>();    // V ready
    __syncthreads();

    // ----- O = P V (P -> fp16 frags), predicated key blocks -----
    float o[16][4];
#pragma unroll
    for (int nt = 0; nt < 16; nt++)
#pragma unroll
        for (int e = 0; e < 4; e++) o[nt][e] = 0.f;

    const int kmax = qt + 1;
#pragma unroll
    for (int kk = 0; kk < 8; kk++) {
        if (kk < kmax) {
            uint32_t aP[4];
            aP[0] = pkh2(__float2half_rn(s[2 * kk][0]),     __float2half_rn(s[2 * kk][1]));
            aP[1] = pkh2(__float2half_rn(s[2 * kk][2]),     __float2half_rn(s[2 * kk][3]));
            aP[2] = pkh2(__float2half_rn(s[2 * kk + 1][0]), __float2half_rn(s[2 * kk + 1][1]));
            aP[3] = pkh2(__float2half_rn(s[2 * kk + 1][2]), __float2half_rn(s[2 * kk + 1][3]));
#pragma unroll
            for (int nt = 0; nt < 16; nt++) {
                uint32_t v[2];
                int l16  = lane & 15;
                int krow = kk * 16 + l16;
                int sw   = nt ^ (krow & 7);
                ldsm2ta(v, smem_u32(sV + krow * 128 + sw * 8));
                mma_h(o[nt], aP, v);
            }
        }
    }

    // ----- epilogue: fp16 (input to proj GEMM) -----
    const size_t tok0 = t0 + r0;
    const size_t tok1 = t0 + r1;
#pragma unroll
    for (int nt = 0; nt < 16; nt++) {
        int col = h * DHEAD + nt * 8 + tq * 2;
        *reinterpret_cast<uint32_t*>(att + tok0 * CDIM + col) =
            pkh2(__float2half_rn(o[nt][0] * inv0), __float2half_rn(o[nt][1] * inv0));
        *reinterpret_cast<uint32_t*>(att + tok1 * CDIM + col) =
            pkh2(__float2half_rn(o[nt][2] * inv1), __float2half_rn(o[nt][3] * inv1));
    }
}

// ---------------------------------------------------------------------------
// Host launcher
// ---------------------------------------------------------------------------
extern "C" void kernel_launch(void* const* d_in, const int* in_sizes, int n_in,
                              void* d_out, int out_size) {
    const float* x  = (const float*)d_in[0];
    const float* wq = (const float*)d_in[1];
    const float* wp = (const float*)d_in[2];
    float* out = (float*)d_out;

    void *pX, *pWq, *pWp, *pQKV, *pA;
    cudaGetSymbolAddress(&pX,   g_X);
    cudaGetSymbolAddress(&pWq,  g_Wq);
    cudaGetSymbolAddress(&pWp,  g_Wp);
    cudaGetSymbolAddress(&pQKV, g_QKV);
    cudaGetSymbolAddress(&pA,   g_A);

    cudaFuncSetAttribute((const void*)gemm_fp16<true>,
                         cudaFuncAttributeMaxDynamicSharedMemorySize, G_SMEM);
    cudaFuncSetAttribute((const void*)gemm_fp16<false>,
                         cudaFuncAttributeMaxDynamicSharedMemorySize, G_SMEM);
    cudaFuncSetAttribute((const void*)attn_kernel,
                         cudaFuncAttributeMaxDynamicSharedMemorySize, 98304);

    // 1) X, Wq, Wp -> fp16 (single fused launch)
    {
        int nx = (MROWS * CDIM) / 4;          // 16,777,216
        int nq = (CDIM * N_QKV) / 4;          //  3,145,728
        int np = (CDIM * CDIM) / 4;           //  1,048,576
        int total = nx + nq + np;
        cvt_all_kernel<<<(total + 255) / 256, 256>>>(
            (const float4*)x,  (uint32_t*)pX,  nx,
            (const float4*)wq, (uint32_t*)pWq, nq,
            (const float4*)wp, (uint32_t*)pWp, np);
    }

    // 2) QKV = X @ Wq -> fp16
    {
        dim3 grid(N_QKV / 128, MROWS / 128);  // (48, 256)
        gemm_fp16<true><<<grid, 128, G_SMEM>>>(
            (const __half*)pX, (const __half*)pWq, nullptr, (__half*)pQKV,
            N_QKV, CDIM);
    }

    // 3) blocked causal attention -> fp16
    attn_kernel<<<BATCH * NBLK * NHEAD, 256, 98304>>>(
        (const __half*)pQKV, (__half*)pA);

    // 4) Y = A @ Wp -> fp32 final output
    {
        dim3 grid(CDIM / 128, MROWS / 128);   // (16, 256)
        gemm_fp16<false><<<grid, 128, G_SMEM>>>(
            (const __half*)pA, (const __half*)pWp, out, nullptr, CDIM, CDIM);
    }
}